// round 9
// baseline (speedup 1.0000x reference)
#include <cuda_runtime.h>
#include <cuda_bf16.h>
#include <stdint.h>
#include <math.h>

#define CB 4
#define CS 2048
#define CD 1024
#define CH 16
#define CDK 64
#define CF 4096
#define MTOT (CB*CS)   // 8192
#define NQKV 3072

#define HG_SMEM (3 * 32768)       // gemm: 3 stages x 32KB = 96KB -> 2 CTA/SM
#define FA_SMEM 81920             // flash: Qh/Ql 16KB + 2 KV stages x 32KB

// ---------------- scratch (device globals; no allocations allowed) ----------
__device__ float g_pr[(size_t)MTOT*CD];
__device__ float g_x1[(size_t)MTOT*CD];
__device__ float g_ff[(size_t)MTOT*CD];

__device__ __nv_bfloat16 g_xh  [(size_t)MTOT*CD],  g_xl  [(size_t)MTOT*CD];
__device__ __nv_bfloat16 g_qkvh[(size_t)MTOT*NQKV], g_qkvl[(size_t)MTOT*NQKV];
__device__ __nv_bfloat16 g_aoh [(size_t)MTOT*CD],  g_aol [(size_t)MTOT*CD];
__device__ __nv_bfloat16 g_x1h [(size_t)MTOT*CD],  g_x1l [(size_t)MTOT*CD];
__device__ __nv_bfloat16 g_hhh [(size_t)MTOT*CF],  g_hhl [(size_t)MTOT*CF];

__device__ __nv_bfloat16 g_wqkv_h[(size_t)NQKV*CD], g_wqkv_l[(size_t)NQKV*CD];
__device__ __nv_bfloat16 g_wo_h[(size_t)CD*CD], g_wo_l[(size_t)CD*CD];
__device__ __nv_bfloat16 g_w1_h[(size_t)CF*CD], g_w1_l[(size_t)CF*CD];
__device__ __nv_bfloat16 g_w2_h[(size_t)CD*CF], g_w2_l[(size_t)CD*CF];
__device__ float g_bqkv[NQKV];

// ---------------- PTX helpers (non-'a' features only) ------------------------
__device__ __forceinline__ uint32_t smem_u32(const void* p) {
    uint32_t a;
    asm("{ .reg .u64 t; cvta.to.shared.u64 t, %1; cvt.u32.u64 %0, t; }" : "=r"(a) : "l"(p));
    return a;
}
__device__ __forceinline__ void cp16(uint32_t dst, const void* src) {
    asm volatile("cp.async.cg.shared.global [%0], [%1], 16;" :: "r"(dst), "l"(src));
}
template<int N> __device__ __forceinline__ void cpwait() {
    asm volatile("cp.async.wait_group %0;" :: "n"(N) : "memory");
}
__device__ __forceinline__ void ldsm4(uint32_t* r, uint32_t addr) {
    asm volatile("ldmatrix.sync.aligned.m8n8.x4.shared.b16 {%0,%1,%2,%3}, [%4];"
                 : "=r"(r[0]), "=r"(r[1]), "=r"(r[2]), "=r"(r[3]) : "r"(addr));
}
__device__ __forceinline__ void ldsm4t(uint32_t* r, uint32_t addr) {
    asm volatile("ldmatrix.sync.aligned.m8n8.x4.trans.shared.b16 {%0,%1,%2,%3}, [%4];"
                 : "=r"(r[0]), "=r"(r[1]), "=r"(r[2]), "=r"(r[3]) : "r"(addr));
}
__device__ __forceinline__ void mma16816(float* c, const uint32_t* a, const uint32_t* b) {
    asm volatile(
        "mma.sync.aligned.m16n8k16.row.col.f32.bf16.bf16.f32 "
        "{%0,%1,%2,%3}, {%4,%5,%6,%7}, {%8,%9}, {%0,%1,%2,%3};"
        : "+f"(c[0]), "+f"(c[1]), "+f"(c[2]), "+f"(c[3])
        : "r"(a[0]), "r"(a[1]), "r"(a[2]), "r"(a[3]), "r"(b[0]), "r"(b[1]));
}
__device__ __forceinline__ float ex2f(float x) {
    float y; asm("ex2.approx.ftz.f32 %0, %1;" : "=f"(y) : "f"(x)); return y;
}
__device__ __forceinline__ uint32_t pack_bf2(float a, float b) {
    __nv_bfloat162 h; h.x = __float2bfloat16(a); h.y = __float2bfloat16(b);
    return *reinterpret_cast<uint32_t*>(&h);
}

// ---------------- mega prep kernel: x-split + 6 transposes + bias concat -----
__global__ __launch_bounds__(256)
void prep_all(const float* __restrict__ x,
              const float* __restrict__ Wq, const float* __restrict__ Wk,
              const float* __restrict__ Wv, const float* __restrict__ Wo,
              const float* __restrict__ W1, const float* __restrict__ W2,
              const float* __restrict__ bq, const float* __restrict__ bk,
              const float* __restrict__ bv)
{
    __shared__ float t[32][33];
    const int blk = blockIdx.x;
    const int tid = threadIdx.x;

    if (blk < 8192) {                       // ---- split x
        int i = blk * 256 + tid;
        float4 v = reinterpret_cast<const float4*>(x)[i];
        __nv_bfloat16 h0 = __float2bfloat16(v.x), h1 = __float2bfloat16(v.y);
        __nv_bfloat16 h2 = __float2bfloat16(v.z), h3 = __float2bfloat16(v.w);
        __nv_bfloat162 a, b;
        a.x = h0; a.y = h1; b.x = h2; b.y = h3;
        reinterpret_cast<__nv_bfloat162*>(g_xh)[2*i]   = a;
        reinterpret_cast<__nv_bfloat162*>(g_xh)[2*i+1] = b;
        a.x = __float2bfloat16(v.x - __bfloat162float(h0));
        a.y = __float2bfloat16(v.y - __bfloat162float(h1));
        b.x = __float2bfloat16(v.z - __bfloat162float(h2));
        b.y = __float2bfloat16(v.w - __bfloat162float(h3));
        reinterpret_cast<__nv_bfloat162*>(g_xl)[2*i]   = a;
        reinterpret_cast<__nv_bfloat162*>(g_xl)[2*i+1] = b;
        return;
    }
    if (blk == 20480) {                     // ---- bias concat
        for (int i = tid; i < NQKV; i += 256)
            g_bqkv[i] = (i < 1024) ? bq[i] : (i < 2048) ? bk[i-1024] : bv[i-2048];
        return;
    }

    int b = blk - 8192;
    const float* W; __nv_bfloat16 *hiT, *loT; int Kd, Nd;
    if      (b < 1024)  { W = Wq; hiT = g_wqkv_h;               loT = g_wqkv_l;               Kd = CD; Nd = CD; }
    else if (b < 2048)  { W = Wk; hiT = g_wqkv_h + 1024u*CD;    loT = g_wqkv_l + 1024u*CD;    Kd = CD; Nd = CD; b -= 1024; }
    else if (b < 3072)  { W = Wv; hiT = g_wqkv_h + 2048u*CD;    loT = g_wqkv_l + 2048u*CD;    Kd = CD; Nd = CD; b -= 2048; }
    else if (b < 4096)  { W = Wo; hiT = g_wo_h;                 loT = g_wo_l;                 Kd = CD; Nd = CD; b -= 3072; }
    else if (b < 8192)  { W = W1; hiT = g_w1_h;                 loT = g_w1_l;                 Kd = CD; Nd = CF; b -= 4096; }
    else                { W = W2; hiT = g_w2_h;                 loT = g_w2_l;                 Kd = CF; Nd = CD; b -= 8192; }

    const int nb = Nd / 32;
    const int n0 = (b % nb) * 32, k0 = (b / nb) * 32;
    const int tx = tid & 31, ty = tid >> 5;
    for (int i = ty; i < 32; i += 8)
        t[i][tx] = W[(size_t)(k0 + i) * Nd + n0 + tx];
    __syncthreads();
    for (int i = ty; i < 32; i += 8) {
        float v = t[tx][i];
        __nv_bfloat16 h = __float2bfloat16(v);
        size_t o = (size_t)(n0 + i) * Kd + k0 + tx;
        hiT[o] = h; loT[o] = __float2bfloat16(v - __bfloat162float(h));
    }
}

// ---------------- HMMA bf16x3 GEMM: fragment-pipelined inner loop ------------
// 128 thr, 4 warps, 64x64 warp tiles, 3-stage ring (96KB, 2 CTA/SM).
// Rolling hi-frag buffers: only one 8-ldsm bubble per chunk; al/bl and next-ks
// hi-frag ldsm issue hidden under mma blocks.
// EPI: 0 = fp32 C, 1 = split hi/lo, 2 = relu + split hi/lo
template<int EPI>
__global__ __launch_bounds__(128, 2)
void hgemm_bf16x3(const __nv_bfloat16* __restrict__ Ah, const __nv_bfloat16* __restrict__ Al,
                  const __nv_bfloat16* __restrict__ Bh, const __nv_bfloat16* __restrict__ Bl,
                  const float* __restrict__ bias, float* __restrict__ C,
                  __nv_bfloat16* __restrict__ Chi, __nv_bfloat16* __restrict__ Clo,
                  int M, int N, int K)
{
    extern __shared__ __align__(1024) char smraw[];
    const uint32_t sbase = smem_u32(smraw);

    const int tid  = threadIdx.x;
    const int lane = tid & 31;
    const int wid  = tid >> 5;          // 0..3
    const int warp_m = wid & 1;
    const int warp_n = wid >> 1;
    const int brow = blockIdx.y, bcol = blockIdx.x;

    const int lr = tid >> 2;            // 0..31
    const int lc = tid & 3;
    const int KC = K >> 5;              // BK=32 chunks

    uint32_t swr[4];
    size_t agr[4], bgr[4];
    #pragma unroll
    for (int rr = 0; rr < 4; ++rr) {
        int r = lr + rr * 32;
        int key = (r >> 1) & 3;
        swr[rr] = (uint32_t)r * 64u + (uint32_t)((lc ^ key) << 4);
        agr[rr] = (size_t)(brow * 128 + r) * (size_t)K;
        bgr[rr] = (size_t)(bcol * 128 + r) * (size_t)K;
    }

    uint32_t a_rb[4]; int a_key[4];
    #pragma unroll
    for (int mt = 0; mt < 4; ++mt) {
        int r = warp_m * 64 + mt * 16 + (lane & 15);
        a_rb[mt] = (uint32_t)r * 64u;
        a_key[mt] = (r >> 1) & 3;
    }
    const int a_ch = lane >> 4;
    uint32_t b_rb[4]; int b_key[4];
    #pragma unroll
    for (int np = 0; np < 4; ++np) {
        int r = warp_n * 64 + np * 16 + (lane & 7) + ((lane >> 4) & 1) * 8;
        b_rb[np] = (uint32_t)r * 64u;
        b_key[np] = (r >> 1) & 3;
    }
    const int b_ch = (lane >> 3) & 1;

    float acc[4][8][4];
    #pragma unroll
    for (int mt = 0; mt < 4; ++mt)
        #pragma unroll
        for (int nt = 0; nt < 8; ++nt)
            #pragma unroll
            for (int r = 0; r < 4; ++r) acc[mt][nt][r] = 0.f;

    auto load_stage = [&](int kk, int s) {
        const size_t ko = (size_t)kk * 32 + (size_t)lc * 8;
        const uint32_t st = sbase + (uint32_t)s * 32768u;
        #pragma unroll
        for (int rr = 0; rr < 4; ++rr) {
            cp16(st +          swr[rr], Ah + agr[rr] + ko);
            cp16(st +  8192u + swr[rr], Al + agr[rr] + ko);
            cp16(st + 16384u + swr[rr], Bh + bgr[rr] + ko);
            cp16(st + 24576u + swr[rr], Bl + bgr[rr] + ko);
        }
        asm volatile("cp.async.commit_group;" ::: "memory");
    };

    load_stage(0, 0);
    if (KC > 1) load_stage(1, 1);

    for (int t = 0; t < KC; ++t) {
        if (t + 1 < KC) cpwait<1>(); else cpwait<0>();
        __syncthreads();
        if (t + 2 < KC) load_stage(t + 2, (t + 2) % 3);

        const uint32_t st = sbase + (uint32_t)(t % 3) * 32768u;

        // ---- fragment-pipelined chunk: ks0 hi frags, then staged ldsm/mma ---
        uint32_t ah0[4][4], bh0[4][4], ah1[4][4], bh1[4][4], alx[4][4], blx[4][4];
        #pragma unroll
        for (int np = 0; np < 4; ++np)
            ldsm4(bh0[np], st + 16384u + b_rb[np] +
                  (uint32_t)((b_ch ^ b_key[np]) << 4));
        #pragma unroll
        for (int mt = 0; mt < 4; ++mt)
            ldsm4(ah0[mt], st + a_rb[mt] +
                  (uint32_t)((a_ch ^ a_key[mt]) << 4));

        // ks = 0 ------------------------------------------------------------
        #pragma unroll
        for (int mt = 0; mt < 4; ++mt)
            ldsm4(alx[mt], st + 8192u + a_rb[mt] +
                  (uint32_t)((a_ch ^ a_key[mt]) << 4));
        #pragma unroll
        for (int np = 0; np < 4; ++np)
            ldsm4(blx[np], st + 24576u + b_rb[np] +
                  (uint32_t)((b_ch ^ b_key[np]) << 4));
        #pragma unroll
        for (int mt = 0; mt < 4; ++mt)
            #pragma unroll
            for (int nt = 0; nt < 8; ++nt)
                mma16816(acc[mt][nt], ah0[mt], &bh0[nt >> 1][(nt & 1) * 2]);
        // prefetch ks=1 hi frags under the lo-pass mma
        #pragma unroll
        for (int np = 0; np < 4; ++np)
            ldsm4(bh1[np], st + 16384u + b_rb[np] +
                  (uint32_t)(((2 + b_ch) ^ b_key[np]) << 4));
        #pragma unroll
        for (int mt = 0; mt < 4; ++mt)
            ldsm4(ah1[mt], st + a_rb[mt] +
                  (uint32_t)(((2 + a_ch) ^ a_key[mt]) << 4));
        #pragma unroll
        for (int mt = 0; mt < 4; ++mt)
            #pragma unroll
            for (int nt = 0; nt < 8; ++nt)
                mma16816(acc[mt][nt], alx[mt], &bh0[nt >> 1][(nt & 1) * 2]);
        #pragma unroll
        for (int mt = 0; mt < 4; ++mt)
            #pragma unroll
            for (int nt = 0; nt < 8; ++nt)
                mma16816(acc[mt][nt], ah0[mt], &blx[nt >> 1][(nt & 1) * 2]);

        // ks = 1 ------------------------------------------------------------
        #pragma unroll
        for (int mt = 0; mt < 4; ++mt)
            ldsm4(alx[mt], st + 8192u + a_rb[mt] +
                  (uint32_t)(((2 + a_ch) ^ a_key[mt]) << 4));
        #pragma unroll
        for (int np = 0; np < 4; ++np)
            ldsm4(blx[np], st + 24576u + b_rb[np] +
                  (uint32_t)(((2 + b_ch) ^ b_key[np]) << 4));
        #pragma unroll
        for (int mt = 0; mt < 4; ++mt)
            #pragma unroll
            for (int nt = 0; nt < 8; ++nt)
                mma16816(acc[mt][nt], ah1[mt], &bh1[nt >> 1][(nt & 1) * 2]);
        #pragma unroll
        for (int mt = 0; mt < 4; ++mt)
            #pragma unroll
            for (int nt = 0; nt < 8; ++nt)
                mma16816(acc[mt][nt], alx[mt], &bh1[nt >> 1][(nt & 1) * 2]);
        #pragma unroll
        for (int mt = 0; mt < 4; ++mt)
            #pragma unroll
            for (int nt = 0; nt < 8; ++nt)
                mma16816(acc[mt][nt], ah1[mt], &blx[nt >> 1][(nt & 1) * 2]);
    }

    const int ng_base = bcol * 128 + warp_n * 64 + (lane & 3) * 2;
    const int mg_base = brow * 128 + warp_m * 64 + (lane >> 2);
    #pragma unroll
    for (int nt = 0; nt < 8; ++nt) {
        const int n = ng_base + nt * 8;
        const float2 bb = *reinterpret_cast<const float2*>(&bias[n]);
        #pragma unroll
        for (int mt = 0; mt < 4; ++mt) {
            const int m0 = mg_base + mt * 16;
            float v0 = acc[mt][nt][0] + bb.x, v1 = acc[mt][nt][1] + bb.y;
            float v2 = acc[mt][nt][2] + bb.x, v3 = acc[mt][nt][3] + bb.y;
            if (EPI == 2) {
                v0 = fmaxf(v0, 0.f); v1 = fmaxf(v1, 0.f);
                v2 = fmaxf(v2, 0.f); v3 = fmaxf(v3, 0.f);
            }
            if (EPI == 0) {
                float2 o0{v0, v1}, o1{v2, v3};
                *reinterpret_cast<float2*>(&C[(size_t)m0 * N + n])       = o0;
                *reinterpret_cast<float2*>(&C[(size_t)(m0 + 8) * N + n]) = o1;
            } else {
                __nv_bfloat162 h0, h1, l0, l1;
                h0.x = __float2bfloat16(v0); h0.y = __float2bfloat16(v1);
                h1.x = __float2bfloat16(v2); h1.y = __float2bfloat16(v3);
                l0.x = __float2bfloat16(v0 - __bfloat162float(h0.x));
                l0.y = __float2bfloat16(v1 - __bfloat162float(h0.y));
                l1.x = __float2bfloat16(v2 - __bfloat162float(h1.x));
                l1.y = __float2bfloat16(v3 - __bfloat162float(h1.y));
                *reinterpret_cast<__nv_bfloat162*>(&Chi[(size_t)m0 * N + n])       = h0;
                *reinterpret_cast<__nv_bfloat162*>(&Chi[(size_t)(m0 + 8) * N + n]) = h1;
                *reinterpret_cast<__nv_bfloat162*>(&Clo[(size_t)m0 * N + n])       = l0;
                *reinterpret_cast<__nv_bfloat162*>(&Clo[(size_t)(m0 + 8) * N + n]) = l1;
            }
        }
    }
}

// ---------------- Flash attention, HMMA bf16x3 (causal), fused QKV input -----
__global__ __launch_bounds__(128)
void flash_hmma(const __nv_bfloat16* __restrict__ QKVh, const __nv_bfloat16* __restrict__ QKVl,
                __nv_bfloat16* __restrict__ Oh, __nv_bfloat16* __restrict__ Ol)
{
    extern __shared__ __align__(1024) char smraw[];
    const uint32_t sb = smem_u32(smraw);
    const uint32_t QHs = sb, QLs = sb + 8192;

    const int qt = (int)gridDim.x - 1 - (int)blockIdx.x;
    const int b  = blockIdx.y >> 4, h = blockIdx.y & 15;
    const int tid = threadIdx.x, lane = tid & 31, warp = tid >> 5;

    const size_t qbase = (size_t)b * CS * NQKV + (size_t)h * CDK;
    const size_t obase = (size_t)b * CS * CD   + (size_t)h * CDK;

    auto load_tile = [&](uint32_t dst, const __nv_bfloat16* src, size_t base, int tile) {
        const __nv_bfloat16* g = src + base + (size_t)tile * 64 * NQKV;
        #pragma unroll
        for (int i = 0; i < 4; ++i) {
            int id = tid + i * 128;
            int r = id >> 3, c = id & 7;
            cp16(dst + (uint32_t)r * 128u + (uint32_t)((c ^ (r & 7)) << 4),
                 g + (size_t)r * NQKV + c * 8);
        }
    };
    auto load_kv = [&](int kt) {
        uint32_t s = sb + 16384u + (uint32_t)(kt & 1) * 32768u;
        load_tile(s,          QKVh, qbase + 1024, kt);
        load_tile(s + 8192u,  QKVl, qbase + 1024, kt);
        load_tile(s + 16384u, QKVh, qbase + 2048, kt);
        load_tile(s + 24576u, QKVl, qbase + 2048, kt);
        asm volatile("cp.async.commit_group;" ::: "memory");
    };

    load_tile(QHs, QKVh, qbase, qt);
    load_tile(QLs, QKVl, qbase, qt);
    load_kv(0);
    cpwait<0>(); __syncthreads();

    uint32_t qfh[4][4], qfl[4][4];
    {
        int r = warp * 16 + (lane & 15);
        uint32_t ro = (uint32_t)r * 128u;
        int key = r & 7;
        #pragma unroll
        for (int ks = 0; ks < 4; ++ks) {
            uint32_t off = ro + (uint32_t)(((ks * 2 + (lane >> 4)) ^ key) << 4);
            ldsm4(qfh[ks], QHs + off);
            ldsm4(qfl[ks], QLs + off);
        }
    }

    float m0 = -1e30f, m1 = -1e30f, l0 = 0.f, l1 = 0.f;
    float oacc[8][4];
    #pragma unroll
    for (int nt = 0; nt < 8; ++nt)
        #pragma unroll
        for (int r = 0; r < 4; ++r) oacc[nt][r] = 0.f;

    const float c1 = 0.18033688011112042f;
    const int r0t = warp * 16 + (lane >> 2);

    for (int kt = 0; kt <= qt; ++kt) {
        if (kt + 1 <= qt) load_kv(kt + 1);
        if (kt > 0) {
            if (kt + 1 <= qt) cpwait<1>(); else cpwait<0>();
            __syncthreads();
        }
        const uint32_t KB  = sb + 16384u + (uint32_t)(kt & 1) * 32768u;
        const uint32_t KLB = KB + 8192u;
        const uint32_t VHB = KB + 16384u;
        const uint32_t VLB = KB + 24576u;

        float sacc[8][4];
        #pragma unroll
        for (int nt = 0; nt < 8; ++nt)
            #pragma unroll
            for (int r = 0; r < 4; ++r) sacc[nt][r] = 0.f;

        #pragma unroll
        for (int ks = 0; ks < 4; ++ks) {
            uint32_t bf[4][4];
            #pragma unroll
            for (int np = 0; np < 4; ++np) {
                int rr = np * 16 + (lane & 7) + ((lane >> 4) & 1) * 8;
                uint32_t chunk = (uint32_t)(ks * 2 + ((lane >> 3) & 1));
                ldsm4(bf[np], KB + (uint32_t)rr * 128u + ((chunk ^ (uint32_t)(rr & 7)) << 4));
            }
            #pragma unroll
            for (int nt = 0; nt < 8; ++nt) {
                mma16816(sacc[nt], qfh[ks], &bf[nt >> 1][(nt & 1) * 2]);
                mma16816(sacc[nt], qfl[ks], &bf[nt >> 1][(nt & 1) * 2]);
            }
        }
        #pragma unroll
        for (int ks = 0; ks < 4; ++ks) {
            uint32_t bf[4][4];
            #pragma unroll
            for (int np = 0; np < 4; ++np) {
                int rr = np * 16 + (lane & 7) + ((lane >> 4) & 1) * 8;
                uint32_t chunk = (uint32_t)(ks * 2 + ((lane >> 3) & 1));
                ldsm4(bf[np], KLB + (uint32_t)rr * 128u + ((chunk ^ (uint32_t)(rr & 7)) << 4));
            }
            #pragma unroll
            for (int nt = 0; nt < 8; ++nt)
                mma16816(sacc[nt], qfh[ks], &bf[nt >> 1][(nt & 1) * 2]);
        }

        const bool diag = (kt == qt);
        float rm0 = -1e30f, rm1 = -1e30f;
        #pragma unroll
        for (int nt = 0; nt < 8; ++nt) {
            const int cb = nt * 8 + 2 * (lane & 3);
            #pragma unroll
            for (int j = 0; j < 2; ++j) {
                float v = sacc[nt][j] * c1;
                if (diag && cb + j > r0t) v = -1e30f;
                sacc[nt][j] = v; rm0 = fmaxf(rm0, v);
                float w = sacc[nt][2 + j] * c1;
                if (diag && cb + j > r0t + 8) w = -1e30f;
                sacc[nt][2 + j] = w; rm1 = fmaxf(rm1, w);
            }
        }
        rm0 = fmaxf(rm0, __shfl_xor_sync(0xffffffffu, rm0, 1));
        rm0 = fmaxf(rm0, __shfl_xor_sync(0xffffffffu, rm0, 2));
        rm1 = fmaxf(rm1, __shfl_xor_sync(0xffffffffu, rm1, 1));
        rm1 = fmaxf(rm1, __shfl_xor_sync(0xffffffffu, rm1, 2));
        const float mn0 = fmaxf(m0, rm0), mn1 = fmaxf(m1, rm1);
        const float corr0 = ex2f(m0 - mn0), corr1 = ex2f(m1 - mn1);
        m0 = mn0; m1 = mn1;

        float ps0 = 0.f, ps1 = 0.f;
        uint32_t pfh[4][4], pfl[4][4];
        #pragma unroll
        for (int nt = 0; nt < 8; ++nt) {
            float p0 = ex2f(sacc[nt][0] - m0);
            float p1 = ex2f(sacc[nt][1] - m0);
            float p2 = ex2f(sacc[nt][2] - m1);
            float p3 = ex2f(sacc[nt][3] - m1);
            ps0 += p0 + p1; ps1 += p2 + p3;
            float h0 = __bfloat162float(__float2bfloat16(p0));
            float h1 = __bfloat162float(__float2bfloat16(p1));
            float h2 = __bfloat162float(__float2bfloat16(p2));
            float h3 = __bfloat162float(__float2bfloat16(p3));
            const int kc = nt >> 1, base = (nt & 1) * 2;
            pfh[kc][base]     = pack_bf2(h0, h1);
            pfh[kc][base + 1] = pack_bf2(h2, h3);
            pfl[kc][base]     = pack_bf2(p0 - h0, p1 - h1);
            pfl[kc][base + 1] = pack_bf2(p2 - h2, p3 - h3);
        }
        ps0 += __shfl_xor_sync(0xffffffffu, ps0, 1);
        ps0 += __shfl_xor_sync(0xffffffffu, ps0, 2);
        ps1 += __shfl_xor_sync(0xffffffffu, ps1, 1);
        ps1 += __shfl_xor_sync(0xffffffffu, ps1, 2);
        l0 = l0 * corr0 + ps0;
        l1 = l1 * corr1 + ps1;

        #pragma unroll
        for (int nt = 0; nt < 8; ++nt) {
            oacc[nt][0] *= corr0; oacc[nt][1] *= corr0;
            oacc[nt][2] *= corr1; oacc[nt][3] *= corr1;
        }

        const int vj  = lane >> 3, vlp = lane & 7;
        #pragma unroll
        for (int kc = 0; kc < 4; ++kc) {
            const int vrow = kc * 16 + (vj & 1) * 8 + vlp;
            const uint32_t vro = (uint32_t)vrow * 128u;
            const uint32_t vkey = (uint32_t)(vrow & 7);
            uint32_t vfh[4][4];
            #pragma unroll
            for (int vb = 0; vb < 4; ++vb) {
                uint32_t chunk = (uint32_t)(vb * 2 + (vj >> 1));
                ldsm4t(vfh[vb], VHB + vro + ((chunk ^ vkey) << 4));
            }
            #pragma unroll
            for (int nt = 0; nt < 8; ++nt) {
                mma16816(oacc[nt], pfh[kc], &vfh[nt >> 1][(nt & 1) * 2]);
                mma16816(oacc[nt], pfl[kc], &vfh[nt >> 1][(nt & 1) * 2]);
            }
            uint32_t vfl[4][4];
            #pragma unroll
            for (int vb = 0; vb < 4; ++vb) {
                uint32_t chunk = (uint32_t)(vb * 2 + (vj >> 1));
                ldsm4t(vfl[vb], VLB + vro + ((chunk ^ vkey) << 4));
            }
            #pragma unroll
            for (int nt = 0; nt < 8; ++nt)
                mma16816(oacc[nt], pfh[kc], &vfl[nt >> 1][(nt & 1) * 2]);
        }
        __syncthreads();
    }

    const float inv0 = 1.f / l0, inv1 = 1.f / l1;
    const size_t row0 = obase + (size_t)(qt * 64 + r0t) * CD;
    const size_t row1 = row0 + (size_t)8 * CD;
    #pragma unroll
    for (int nt = 0; nt < 8; ++nt) {
        const int cb = nt * 8 + 2 * (lane & 3);
        float v0 = oacc[nt][0] * inv0, v1 = oacc[nt][1] * inv0;
        float v2 = oacc[nt][2] * inv1, v3 = oacc[nt][3] * inv1;
        float h0 = __bfloat162float(__float2bfloat16(v0));
        float h1 = __bfloat162float(__float2bfloat16(v1));
        float h2 = __bfloat162float(__float2bfloat16(v2));
        float h3 = __bfloat162float(__float2bfloat16(v3));
        *reinterpret_cast<uint32_t*>(&Oh[row0 + cb]) = pack_bf2(h0, h1);
        *reinterpret_cast<uint32_t*>(&Oh[row1 + cb]) = pack_bf2(h2, h3);
        *reinterpret_cast<uint32_t*>(&Ol[row0 + cb]) = pack_bf2(v0 - h0, v1 - h1);
        *reinterpret_cast<uint32_t*>(&Ol[row1 + cb]) = pack_bf2(v2 - h2, v3 - h3);
    }
}

// ---------------- residual + LayerNorm (optional split outputs) --------------
__global__ __launch_bounds__(256)
void residual_ln(const float* __restrict__ x, const float* __restrict__ r,
                 const float* __restrict__ gamma, const float* __restrict__ beta,
                 float* __restrict__ out,
                 __nv_bfloat16* __restrict__ outh, __nv_bfloat16* __restrict__ outl)
{
    const int row = blockIdx.x;
    const int tid = threadIdx.x;
    const float4 a = reinterpret_cast<const float4*>(x + (size_t)row * CD)[tid];
    const float4 c = reinterpret_cast<const float4*>(r + (size_t)row * CD)[tid];
    float v0 = a.x + c.x, v1 = a.y + c.y, v2 = a.z + c.z, v3 = a.w + c.w;
    float s  = v0 + v1 + v2 + v3;
    float sq = v0 * v0 + v1 * v1 + v2 * v2 + v3 * v3;

    #pragma unroll
    for (int o = 16; o; o >>= 1) {
        s  += __shfl_xor_sync(0xffffffffu, s,  o);
        sq += __shfl_xor_sync(0xffffffffu, sq, o);
    }
    __shared__ float ss[8], sg[8];
    const int w = tid >> 5, lane = tid & 31;
    if (lane == 0) { ss[w] = s; sg[w] = sq; }
    __syncthreads();
    if (w == 0) {
        s  = (lane < 8) ? ss[lane] : 0.f;
        sq = (lane < 8) ? sg[lane] : 0.f;
        #pragma unroll
        for (int o = 4; o; o >>= 1) {
            s  += __shfl_xor_sync(0xffffffffu, s,  o);
            sq += __shfl_xor_sync(0xffffffffu, sq, o);
        }
        if (lane == 0) { ss[0] = s; sg[0] = sq; }
    }
    __syncthreads();
    s = ss[0]; sq = sg[0];

    const float mu  = s * (1.f / CD);
    const float var = sq * (1.f / CD) - mu * mu;
    const float inv = rsqrtf(var + 1e-5f);

    const float4 gv = reinterpret_cast<const float4*>(gamma)[tid];
    const float4 bv = reinterpret_cast<const float4*>(beta)[tid];
    float4 o4;
    o4.x = (v0 - mu) * inv * gv.x + bv.x;
    o4.y = (v1 - mu) * inv * gv.y + bv.y;
    o4.z = (v2 - mu) * inv * gv.z + bv.z;
    o4.w = (v3 - mu) * inv * gv.w + bv.w;
    reinterpret_cast<float4*>(out + (size_t)row * CD)[tid] = o4;

    if (outh) {
        __nv_bfloat162 h0, h1, lo0, lo1;
        h0.x = __float2bfloat16(o4.x); h0.y = __float2bfloat16(o4.y);
        h1.x = __float2bfloat16(o4.z); h1.y = __float2bfloat16(o4.w);
        lo0.x = __float2bfloat16(o4.x - __bfloat162float(h0.x));
        lo0.y = __float2bfloat16(o4.y - __bfloat162float(h0.y));
        lo1.x = __float2bfloat16(o4.z - __bfloat162float(h1.x));
        lo1.y = __float2bfloat16(o4.w - __bfloat162float(h1.y));
        reinterpret_cast<__nv_bfloat162*>(outh + (size_t)row * CD)[2*tid]   = h0;
        reinterpret_cast<__nv_bfloat162*>(outh + (size_t)row * CD)[2*tid+1] = h1;
        reinterpret_cast<__nv_bfloat162*>(outl + (size_t)row * CD)[2*tid]   = lo0;
        reinterpret_cast<__nv_bfloat162*>(outl + (size_t)row * CD)[2*tid+1] = lo1;
    }
}

// ---------------- launch -----------------------------------------------------
extern "C" void kernel_launch(void* const* d_in, const int* in_sizes, int n_in,
                              void* d_out, int out_size)
{
    const float* x  = (const float*)d_in[0];
    const float* Wq = (const float*)d_in[2];
    const float* bq = (const float*)d_in[3];
    const float* Wk = (const float*)d_in[4];
    const float* bk = (const float*)d_in[5];
    const float* Wv = (const float*)d_in[6];
    const float* bv = (const float*)d_in[7];
    const float* Wo = (const float*)d_in[8];
    const float* bo = (const float*)d_in[9];
    const float* g1 = (const float*)d_in[10];
    const float* b1 = (const float*)d_in[11];
    const float* W1 = (const float*)d_in[12];
    const float* c1 = (const float*)d_in[13];
    const float* W2 = (const float*)d_in[14];
    const float* c2 = (const float*)d_in[15];
    const float* g2 = (const float*)d_in[16];
    const float* b2 = (const float*)d_in[17];
    float* out = (float*)d_out;

    float *pr, *x1, *ff, *bqkv;
    cudaGetSymbolAddress((void**)&pr, g_pr);
    cudaGetSymbolAddress((void**)&x1, g_x1);
    cudaGetSymbolAddress((void**)&ff, g_ff);
    cudaGetSymbolAddress((void**)&bqkv, g_bqkv);

    __nv_bfloat16 *xh,*xl,*qkvh,*qkvl,*aoh,*aol,*x1h,*x1l,*hhh,*hhl;
    cudaGetSymbolAddress((void**)&xh,   g_xh);   cudaGetSymbolAddress((void**)&xl,   g_xl);
    cudaGetSymbolAddress((void**)&qkvh, g_qkvh); cudaGetSymbolAddress((void**)&qkvl, g_qkvl);
    cudaGetSymbolAddress((void**)&aoh,  g_aoh);  cudaGetSymbolAddress((void**)&aol,  g_aol);
    cudaGetSymbolAddress((void**)&x1h,  g_x1h);  cudaGetSymbolAddress((void**)&x1l,  g_x1l);
    cudaGetSymbolAddress((void**)&hhh,  g_hhh);  cudaGetSymbolAddress((void**)&hhl,  g_hhl);

    __nv_bfloat16 *wqkvh,*wqkvl,*woh,*wol,*w1h,*w1l,*w2h,*w2l;
    cudaGetSymbolAddress((void**)&wqkvh, g_wqkv_h); cudaGetSymbolAddress((void**)&wqkvl, g_wqkv_l);
    cudaGetSymbolAddress((void**)&woh, g_wo_h); cudaGetSymbolAddress((void**)&wol, g_wo_l);
    cudaGetSymbolAddress((void**)&w1h, g_w1_h); cudaGetSymbolAddress((void**)&w1l, g_w1_l);
    cudaGetSymbolAddress((void**)&w2h, g_w2_h); cudaGetSymbolAddress((void**)&w2l, g_w2_l);

    cudaFuncSetAttribute(flash_hmma, cudaFuncAttributeMaxDynamicSharedMemorySize, FA_SMEM);
    cudaFuncSetAttribute(hgemm_bf16x3<0>, cudaFuncAttributeMaxDynamicSharedMemorySize, HG_SMEM);
    cudaFuncSetAttribute(hgemm_bf16x3<1>, cudaFuncAttributeMaxDynamicSharedMemorySize, HG_SMEM);
    cudaFuncSetAttribute(hgemm_bf16x3<2>, cudaFuncAttributeMaxDynamicSharedMemorySize, HG_SMEM);

    prep_all<<<20481, 256>>>(x, Wq, Wk, Wv, Wo, W1, W2, bq, bk, bv);

    dim3 gQKV(NQKV / 128, MTOT / 128);
    dim3 gD(CD / 128, MTOT / 128);
    dim3 gF(CF / 128, MTOT / 128);

    hgemm_bf16x3<1><<<gQKV, 128, HG_SMEM>>>(xh, xl, wqkvh, wqkvl, bqkv,
                                            nullptr, qkvh, qkvl, MTOT, NQKV, CD);

    flash_hmma<<<dim3(CS / 64, CB * CH), 128, FA_SMEM>>>(qkvh, qkvl, aoh, aol);

    hgemm_bf16x3<0><<<gD, 128, HG_SMEM>>>(aoh, aol, woh, wol, bo, pr, nullptr, nullptr, MTOT, CD, CD);
    residual_ln<<<MTOT, 256>>>(x, pr, g1, b1, x1, x1h, x1l);

    hgemm_bf16x3<2><<<gF, 128, HG_SMEM>>>(x1h, x1l, w1h, w1l, c1, nullptr, hhh, hhl, MTOT, CF, CD);
    hgemm_bf16x3<0><<<gD, 128, HG_SMEM>>>(hhh, hhl, w2h, w2l, c2, ff, nullptr, nullptr, MTOT, CD, CF);
    residual_ln<<<MTOT, 256>>>(x1, ff, g2, b2, out, nullptr, nullptr);
}

// round 10
// speedup vs baseline: 1.2084x; 1.2084x over previous
#include <cuda_runtime.h>
#include <cuda_bf16.h>
#include <cuda_fp16.h>
#include <stdint.h>
#include <math.h>

#define CB 4
#define CS 2048
#define CD 1024
#define CH 16
#define CDK 64
#define CF 4096
#define MTOT (CB*CS)   // 8192
#define NQKV 3072

#define HG_SMEM (3 * 32768)       // bf16x3 gemm: 3 stages x 32KB = 96KB -> 2 CTA/SM
#define HF_SMEM (4 * 24576)       // fp16x2 gemm: 4 stages x 24KB = 96KB -> 2 CTA/SM
#define FA_SMEM 81920             // flash: Qh/Ql 16KB + 2 KV stages x 32KB

// ---------------- scratch (device globals; no allocations allowed) ----------
__device__ float g_pr[(size_t)MTOT*CD];
__device__ float g_x1[(size_t)MTOT*CD];
__device__ float g_ff[(size_t)MTOT*CD];

__device__ __nv_bfloat16 g_xh  [(size_t)MTOT*CD],  g_xl  [(size_t)MTOT*CD];
__device__ __nv_bfloat16 g_qkvh[(size_t)MTOT*NQKV], g_qkvl[(size_t)MTOT*NQKV];
__device__ __half        g_aoh [(size_t)MTOT*CD],  g_aol [(size_t)MTOT*CD];
__device__ __half        g_x1h [(size_t)MTOT*CD],  g_x1l [(size_t)MTOT*CD];
__device__ __half        g_hhh [(size_t)MTOT*CF],  g_hhl [(size_t)MTOT*CF];

__device__ __nv_bfloat16 g_wqkv_h[(size_t)NQKV*CD], g_wqkv_l[(size_t)NQKV*CD];
__device__ __half g_wo[(size_t)CD*CD];
__device__ __half g_w1[(size_t)CF*CD];
__device__ __half g_w2[(size_t)CD*CF];
__device__ float g_bqkv[NQKV];

// ---------------- PTX helpers (non-'a' features only) ------------------------
__device__ __forceinline__ uint32_t smem_u32(const void* p) {
    uint32_t a;
    asm("{ .reg .u64 t; cvta.to.shared.u64 t, %1; cvt.u32.u64 %0, t; }" : "=r"(a) : "l"(p));
    return a;
}
__device__ __forceinline__ void cp16(uint32_t dst, const void* src) {
    asm volatile("cp.async.cg.shared.global [%0], [%1], 16;" :: "r"(dst), "l"(src));
}
template<int N> __device__ __forceinline__ void cpwait() {
    asm volatile("cp.async.wait_group %0;" :: "n"(N) : "memory");
}
__device__ __forceinline__ void ldsm4(uint32_t* r, uint32_t addr) {
    asm volatile("ldmatrix.sync.aligned.m8n8.x4.shared.b16 {%0,%1,%2,%3}, [%4];"
                 : "=r"(r[0]), "=r"(r[1]), "=r"(r[2]), "=r"(r[3]) : "r"(addr));
}
__device__ __forceinline__ void ldsm4t(uint32_t* r, uint32_t addr) {
    asm volatile("ldmatrix.sync.aligned.m8n8.x4.trans.shared.b16 {%0,%1,%2,%3}, [%4];"
                 : "=r"(r[0]), "=r"(r[1]), "=r"(r[2]), "=r"(r[3]) : "r"(addr));
}
__device__ __forceinline__ void mma16816(float* c, const uint32_t* a, const uint32_t* b) {
    asm volatile(
        "mma.sync.aligned.m16n8k16.row.col.f32.bf16.bf16.f32 "
        "{%0,%1,%2,%3}, {%4,%5,%6,%7}, {%8,%9}, {%0,%1,%2,%3};"
        : "+f"(c[0]), "+f"(c[1]), "+f"(c[2]), "+f"(c[3])
        : "r"(a[0]), "r"(a[1]), "r"(a[2]), "r"(a[3]), "r"(b[0]), "r"(b[1]));
}
__device__ __forceinline__ void mma16816h(float* c, const uint32_t* a, const uint32_t* b) {
    asm volatile(
        "mma.sync.aligned.m16n8k16.row.col.f32.f16.f16.f32 "
        "{%0,%1,%2,%3}, {%4,%5,%6,%7}, {%8,%9}, {%0,%1,%2,%3};"
        : "+f"(c[0]), "+f"(c[1]), "+f"(c[2]), "+f"(c[3])
        : "r"(a[0]), "r"(a[1]), "r"(a[2]), "r"(a[3]), "r"(b[0]), "r"(b[1]));
}
__device__ __forceinline__ float ex2f(float x) {
    float y; asm("ex2.approx.ftz.f32 %0, %1;" : "=f"(y) : "f"(x)); return y;
}
__device__ __forceinline__ uint32_t pack_bf2(float a, float b) {
    __nv_bfloat162 h; h.x = __float2bfloat16(a); h.y = __float2bfloat16(b);
    return *reinterpret_cast<uint32_t*>(&h);
}
__device__ __forceinline__ uint32_t pack_hf2(float a, float b) {
    __half2 h; h.x = __float2half(a); h.y = __float2half(b);
    return *reinterpret_cast<uint32_t*>(&h);
}

// ---------------- mega prep kernel -------------------------------------------
// blocks [0,8192): split x (bf16). [8192,20480): weight converts. [20480]: bias.
__global__ __launch_bounds__(256)
void prep_all(const float* __restrict__ x,
              const float* __restrict__ Wq, const float* __restrict__ Wk,
              const float* __restrict__ Wv, const float* __restrict__ Wo,
              const float* __restrict__ W1, const float* __restrict__ W2,
              const float* __restrict__ bq, const float* __restrict__ bk,
              const float* __restrict__ bv)
{
    __shared__ float t[32][33];
    const int blk = blockIdx.x;
    const int tid = threadIdx.x;

    if (blk < 8192) {                       // ---- split x (bf16 hi/lo)
        int i = blk * 256 + tid;
        float4 v = reinterpret_cast<const float4*>(x)[i];
        __nv_bfloat16 h0 = __float2bfloat16(v.x), h1 = __float2bfloat16(v.y);
        __nv_bfloat16 h2 = __float2bfloat16(v.z), h3 = __float2bfloat16(v.w);
        __nv_bfloat162 a, b;
        a.x = h0; a.y = h1; b.x = h2; b.y = h3;
        reinterpret_cast<__nv_bfloat162*>(g_xh)[2*i]   = a;
        reinterpret_cast<__nv_bfloat162*>(g_xh)[2*i+1] = b;
        a.x = __float2bfloat16(v.x - __bfloat162float(h0));
        a.y = __float2bfloat16(v.y - __bfloat162float(h1));
        b.x = __float2bfloat16(v.z - __bfloat162float(h2));
        b.y = __float2bfloat16(v.w - __bfloat162float(h3));
        reinterpret_cast<__nv_bfloat162*>(g_xl)[2*i]   = a;
        reinterpret_cast<__nv_bfloat162*>(g_xl)[2*i+1] = b;
        return;
    }
    if (blk == 20480) {                     // ---- bias concat
        for (int i = tid; i < NQKV; i += 256)
            g_bqkv[i] = (i < 1024) ? bq[i] : (i < 2048) ? bk[i-1024] : bv[i-2048];
        return;
    }

    int b = blk - 8192;
    const float* W; int Kd, Nd;
    __nv_bfloat16 *hiT = nullptr, *loT = nullptr;   // bf16 pair path (QKV)
    __half *hT = nullptr;                            // fp16 single path (Wo/W1/W2)
    if      (b < 1024)  { W = Wq; hiT = g_wqkv_h;            loT = g_wqkv_l;            Kd = CD; Nd = CD; }
    else if (b < 2048)  { W = Wk; hiT = g_wqkv_h + 1024u*CD; loT = g_wqkv_l + 1024u*CD; Kd = CD; Nd = CD; b -= 1024; }
    else if (b < 3072)  { W = Wv; hiT = g_wqkv_h + 2048u*CD; loT = g_wqkv_l + 2048u*CD; Kd = CD; Nd = CD; b -= 2048; }
    else if (b < 4096)  { W = Wo; hT = g_wo; Kd = CD; Nd = CD; b -= 3072; }
    else if (b < 8192)  { W = W1; hT = g_w1; Kd = CD; Nd = CF; b -= 4096; }
    else                { W = W2; hT = g_w2; Kd = CF; Nd = CD; b -= 8192; }

    const int nb = Nd / 32;
    const int n0 = (b % nb) * 32, k0 = (b / nb) * 32;
    const int tx = tid & 31, ty = tid >> 5;
    for (int i = ty; i < 32; i += 8)
        t[i][tx] = W[(size_t)(k0 + i) * Nd + n0 + tx];
    __syncthreads();
    for (int i = ty; i < 32; i += 8) {
        float v = t[tx][i];
        size_t o = (size_t)(n0 + i) * Kd + k0 + tx;
        if (hT) {
            hT[o] = __float2half(v);
        } else {
            __nv_bfloat16 h = __float2bfloat16(v);
            hiT[o] = h; loT[o] = __float2bfloat16(v - __bfloat162float(h));
        }
    }
}

// ---------------- HMMA bf16x3 GEMM (QKV only) --------------------------------
// 128 thr, 4 warps, 64x64 warp tiles, 3-stage ring (96KB, 2 CTA/SM).
__global__ __launch_bounds__(128, 2)
void hgemm_bf16x3(const __nv_bfloat16* __restrict__ Ah, const __nv_bfloat16* __restrict__ Al,
                  const __nv_bfloat16* __restrict__ Bh, const __nv_bfloat16* __restrict__ Bl,
                  const float* __restrict__ bias,
                  __nv_bfloat16* __restrict__ Chi, __nv_bfloat16* __restrict__ Clo,
                  int M, int N, int K)
{
    extern __shared__ __align__(1024) char smraw[];
    const uint32_t sbase = smem_u32(smraw);

    const int tid  = threadIdx.x;
    const int lane = tid & 31;
    const int wid  = tid >> 5;
    const int warp_m = wid & 1;
    const int warp_n = wid >> 1;
    const int brow = blockIdx.y, bcol = blockIdx.x;

    const int lr = tid >> 2;
    const int lc = tid & 3;
    const int KC = K >> 5;

    uint32_t swr[4];
    size_t agr[4], bgr[4];
    #pragma unroll
    for (int rr = 0; rr < 4; ++rr) {
        int r = lr + rr * 32;
        int key = (r >> 1) & 3;
        swr[rr] = (uint32_t)r * 64u + (uint32_t)((lc ^ key) << 4);
        agr[rr] = (size_t)(brow * 128 + r) * (size_t)K;
        bgr[rr] = (size_t)(bcol * 128 + r) * (size_t)K;
    }

    uint32_t a_rb[4]; int a_key[4];
    #pragma unroll
    for (int mt = 0; mt < 4; ++mt) {
        int r = warp_m * 64 + mt * 16 + (lane & 15);
        a_rb[mt] = (uint32_t)r * 64u;
        a_key[mt] = (r >> 1) & 3;
    }
    const int a_ch = lane >> 4;
    uint32_t b_rb[4]; int b_key[4];
    #pragma unroll
    for (int np = 0; np < 4; ++np) {
        int r = warp_n * 64 + np * 16 + (lane & 7) + ((lane >> 4) & 1) * 8;
        b_rb[np] = (uint32_t)r * 64u;
        b_key[np] = (r >> 1) & 3;
    }
    const int b_ch = (lane >> 3) & 1;

    float acc[4][8][4];
    #pragma unroll
    for (int mt = 0; mt < 4; ++mt)
        #pragma unroll
        for (int nt = 0; nt < 8; ++nt)
            #pragma unroll
            for (int r = 0; r < 4; ++r) acc[mt][nt][r] = 0.f;

    auto load_stage = [&](int kk, int s) {
        const size_t ko = (size_t)kk * 32 + (size_t)lc * 8;
        const uint32_t st = sbase + (uint32_t)s * 32768u;
        #pragma unroll
        for (int rr = 0; rr < 4; ++rr) {
            cp16(st +          swr[rr], Ah + agr[rr] + ko);
            cp16(st +  8192u + swr[rr], Al + agr[rr] + ko);
            cp16(st + 16384u + swr[rr], Bh + bgr[rr] + ko);
            cp16(st + 24576u + swr[rr], Bl + bgr[rr] + ko);
        }
        asm volatile("cp.async.commit_group;" ::: "memory");
    };

    load_stage(0, 0);
    if (KC > 1) load_stage(1, 1);

    for (int t = 0; t < KC; ++t) {
        if (t + 1 < KC) cpwait<1>(); else cpwait<0>();
        __syncthreads();
        if (t + 2 < KC) load_stage(t + 2, (t + 2) % 3);

        const uint32_t st = sbase + (uint32_t)(t % 3) * 32768u;
        #pragma unroll
        for (int ks = 0; ks < 2; ++ks) {
            uint32_t bh[4][4];
            #pragma unroll
            for (int np = 0; np < 4; ++np)
                ldsm4(bh[np], st + 16384u + b_rb[np] +
                      (uint32_t)((((ks << 1) + b_ch) ^ b_key[np]) << 4));
            uint32_t ah[4][4];
            #pragma unroll
            for (int mt = 0; mt < 4; ++mt)
                ldsm4(ah[mt], st + a_rb[mt] +
                      (uint32_t)((((ks << 1) + a_ch) ^ a_key[mt]) << 4));
            #pragma unroll
            for (int mt = 0; mt < 4; ++mt)
                #pragma unroll
                for (int nt = 0; nt < 8; ++nt)
                    mma16816(acc[mt][nt], ah[mt], &bh[nt >> 1][(nt & 1) * 2]);
            {
                uint32_t al[4][4];
                #pragma unroll
                for (int mt = 0; mt < 4; ++mt)
                    ldsm4(al[mt], st + 8192u + a_rb[mt] +
                          (uint32_t)((((ks << 1) + a_ch) ^ a_key[mt]) << 4));
                #pragma unroll
                for (int mt = 0; mt < 4; ++mt)
                    #pragma unroll
                    for (int nt = 0; nt < 8; ++nt)
                        mma16816(acc[mt][nt], al[mt], &bh[nt >> 1][(nt & 1) * 2]);
            }
            {
                uint32_t bl[4][4];
                #pragma unroll
                for (int np = 0; np < 4; ++np)
                    ldsm4(bl[np], st + 24576u + b_rb[np] +
                          (uint32_t)((((ks << 1) + b_ch) ^ b_key[np]) << 4));
                #pragma unroll
                for (int mt = 0; mt < 4; ++mt)
                    #pragma unroll
                    for (int nt = 0; nt < 8; ++nt)
                        mma16816(acc[mt][nt], ah[mt], &bl[nt >> 1][(nt & 1) * 2]);
            }
        }
    }

    const int ng_base = bcol * 128 + warp_n * 64 + (lane & 3) * 2;
    const int mg_base = brow * 128 + warp_m * 64 + (lane >> 2);
    #pragma unroll
    for (int nt = 0; nt < 8; ++nt) {
        const int n = ng_base + nt * 8;
        const float2 bb = *reinterpret_cast<const float2*>(&bias[n]);
        #pragma unroll
        for (int mt = 0; mt < 4; ++mt) {
            const int m0 = mg_base + mt * 16;
            float v0 = acc[mt][nt][0] + bb.x, v1 = acc[mt][nt][1] + bb.y;
            float v2 = acc[mt][nt][2] + bb.x, v3 = acc[mt][nt][3] + bb.y;
            __nv_bfloat162 h0, h1, l0, l1;
            h0.x = __float2bfloat16(v0); h0.y = __float2bfloat16(v1);
            h1.x = __float2bfloat16(v2); h1.y = __float2bfloat16(v3);
            l0.x = __float2bfloat16(v0 - __bfloat162float(h0.x));
            l0.y = __float2bfloat16(v1 - __bfloat162float(h0.y));
            l1.x = __float2bfloat16(v2 - __bfloat162float(h1.x));
            l1.y = __float2bfloat16(v3 - __bfloat162float(h1.y));
            *reinterpret_cast<__nv_bfloat162*>(&Chi[(size_t)m0 * N + n])       = h0;
            *reinterpret_cast<__nv_bfloat162*>(&Chi[(size_t)(m0 + 8) * N + n]) = h1;
            *reinterpret_cast<__nv_bfloat162*>(&Clo[(size_t)m0 * N + n])       = l0;
            *reinterpret_cast<__nv_bfloat162*>(&Clo[(size_t)(m0 + 8) * N + n]) = l1;
        }
    }
}

// ---------------- HMMA fp16x2 GEMM (Wo/W1/W2) --------------------------------
// C = (Ah+Al)[M,K] @ B[N,K]^T + bias, A fp16 hi/lo (near-exact), B single fp16.
// 128 thr, 4 warps, 64x64 warp tiles, 4-stage ring (96KB, 2 CTA/SM).
// EPI: 0 = fp32 C, 2 = relu + fp16 hi/lo split
template<int EPI>
__global__ __launch_bounds__(128, 2)
void hgemm_fp16x2(const __half* __restrict__ Ah, const __half* __restrict__ Al,
                  const __half* __restrict__ B,
                  const float* __restrict__ bias, float* __restrict__ C,
                  __half* __restrict__ Chi, __half* __restrict__ Clo,
                  int M, int N, int K)
{
    extern __shared__ __align__(1024) char smraw[];
    const uint32_t sbase = smem_u32(smraw);

    const int tid  = threadIdx.x;
    const int lane = tid & 31;
    const int wid  = tid >> 5;
    const int warp_m = wid & 1;
    const int warp_n = wid >> 1;
    const int brow = blockIdx.y, bcol = blockIdx.x;

    const int lr = tid >> 2;
    const int lc = tid & 3;
    const int KC = K >> 5;

    uint32_t swr[4];
    size_t agr[4], bgr[4];
    #pragma unroll
    for (int rr = 0; rr < 4; ++rr) {
        int r = lr + rr * 32;
        int key = (r >> 1) & 3;
        swr[rr] = (uint32_t)r * 64u + (uint32_t)((lc ^ key) << 4);
        agr[rr] = (size_t)(brow * 128 + r) * (size_t)K;
        bgr[rr] = (size_t)(bcol * 128 + r) * (size_t)K;
    }

    uint32_t a_rb[4]; int a_key[4];
    #pragma unroll
    for (int mt = 0; mt < 4; ++mt) {
        int r = warp_m * 64 + mt * 16 + (lane & 15);
        a_rb[mt] = (uint32_t)r * 64u;
        a_key[mt] = (r >> 1) & 3;
    }
    const int a_ch = lane >> 4;
    uint32_t b_rb[4]; int b_key[4];
    #pragma unroll
    for (int np = 0; np < 4; ++np) {
        int r = warp_n * 64 + np * 16 + (lane & 7) + ((lane >> 4) & 1) * 8;
        b_rb[np] = (uint32_t)r * 64u;
        b_key[np] = (r >> 1) & 3;
    }
    const int b_ch = (lane >> 3) & 1;

    float acc[4][8][4];
    #pragma unroll
    for (int mt = 0; mt < 4; ++mt)
        #pragma unroll
        for (int nt = 0; nt < 8; ++nt)
            #pragma unroll
            for (int r = 0; r < 4; ++r) acc[mt][nt][r] = 0.f;

    // stage = Ah(8KB) | Al(8KB) | B(8KB)
    auto load_stage = [&](int kk, int s) {
        const size_t ko = (size_t)kk * 32 + (size_t)lc * 8;
        const uint32_t st = sbase + (uint32_t)s * 24576u;
        #pragma unroll
        for (int rr = 0; rr < 4; ++rr) {
            cp16(st +          swr[rr], Ah + agr[rr] + ko);
            cp16(st +  8192u + swr[rr], Al + agr[rr] + ko);
            cp16(st + 16384u + swr[rr], B  + bgr[rr] + ko);
        }
        asm volatile("cp.async.commit_group;" ::: "memory");
    };

    load_stage(0, 0);
    if (KC > 1) load_stage(1, 1);
    if (KC > 2) load_stage(2, 2);

    for (int t = 0; t < KC; ++t) {
        if (t + 2 < KC) cpwait<2>(); else if (t + 1 < KC) cpwait<1>(); else cpwait<0>();
        __syncthreads();
        if (t + 3 < KC) load_stage(t + 3, (t + 3) & 3);

        const uint32_t st = sbase + (uint32_t)(t & 3) * 24576u;
        #pragma unroll
        for (int ks = 0; ks < 2; ++ks) {
            uint32_t bf[4][4];
            #pragma unroll
            for (int np = 0; np < 4; ++np)
                ldsm4(bf[np], st + 16384u + b_rb[np] +
                      (uint32_t)((((ks << 1) + b_ch) ^ b_key[np]) << 4));
            uint32_t ah[4][4];
            #pragma unroll
            for (int mt = 0; mt < 4; ++mt)
                ldsm4(ah[mt], st + a_rb[mt] +
                      (uint32_t)((((ks << 1) + a_ch) ^ a_key[mt]) << 4));
            #pragma unroll
            for (int mt = 0; mt < 4; ++mt)
                #pragma unroll
                for (int nt = 0; nt < 8; ++nt)
                    mma16816h(acc[mt][nt], ah[mt], &bf[nt >> 1][(nt & 1) * 2]);
            {
                uint32_t al[4][4];
                #pragma unroll
                for (int mt = 0; mt < 4; ++mt)
                    ldsm4(al[mt], st + 8192u + a_rb[mt] +
                          (uint32_t)((((ks << 1) + a_ch) ^ a_key[mt]) << 4));
                #pragma unroll
                for (int mt = 0; mt < 4; ++mt)
                    #pragma unroll
                    for (int nt = 0; nt < 8; ++nt)
                        mma16816h(acc[mt][nt], al[mt], &bf[nt >> 1][(nt & 1) * 2]);
            }
        }
    }

    const int ng_base = bcol * 128 + warp_n * 64 + (lane & 3) * 2;
    const int mg_base = brow * 128 + warp_m * 64 + (lane >> 2);
    #pragma unroll
    for (int nt = 0; nt < 8; ++nt) {
        const int n = ng_base + nt * 8;
        const float2 bb = *reinterpret_cast<const float2*>(&bias[n]);
        #pragma unroll
        for (int mt = 0; mt < 4; ++mt) {
            const int m0 = mg_base + mt * 16;
            float v0 = acc[mt][nt][0] + bb.x, v1 = acc[mt][nt][1] + bb.y;
            float v2 = acc[mt][nt][2] + bb.x, v3 = acc[mt][nt][3] + bb.y;
            if (EPI == 2) {
                v0 = fmaxf(v0, 0.f); v1 = fmaxf(v1, 0.f);
                v2 = fmaxf(v2, 0.f); v3 = fmaxf(v3, 0.f);
            }
            if (EPI == 0) {
                float2 o0{v0, v1}, o1{v2, v3};
                *reinterpret_cast<float2*>(&C[(size_t)m0 * N + n])       = o0;
                *reinterpret_cast<float2*>(&C[(size_t)(m0 + 8) * N + n]) = o1;
            } else {
                __half2 h0, h1, l0, l1;
                h0.x = __float2half(v0); h0.y = __float2half(v1);
                h1.x = __float2half(v2); h1.y = __float2half(v3);
                l0.x = __float2half(v0 - __half2float(h0.x));
                l0.y = __float2half(v1 - __half2float(h0.y));
                l1.x = __float2half(v2 - __half2float(h1.x));
                l1.y = __float2half(v3 - __half2float(h1.y));
                *reinterpret_cast<__half2*>(&Chi[(size_t)m0 * N + n])       = h0;
                *reinterpret_cast<__half2*>(&Chi[(size_t)(m0 + 8) * N + n]) = h1;
                *reinterpret_cast<__half2*>(&Clo[(size_t)m0 * N + n])       = l0;
                *reinterpret_cast<__half2*>(&Clo[(size_t)(m0 + 8) * N + n]) = l1;
            }
        }
    }
}

// ---------------- Flash attention, HMMA bf16x3 (causal), fp16 output ---------
__global__ __launch_bounds__(128)
void flash_hmma(const __nv_bfloat16* __restrict__ QKVh, const __nv_bfloat16* __restrict__ QKVl,
                __half* __restrict__ Oh, __half* __restrict__ Ol)
{
    extern __shared__ __align__(1024) char smraw[];
    const uint32_t sb = smem_u32(smraw);
    const uint32_t QHs = sb, QLs = sb + 8192;

    const int qt = (int)gridDim.x - 1 - (int)blockIdx.x;
    const int b  = blockIdx.y >> 4, h = blockIdx.y & 15;
    const int tid = threadIdx.x, lane = tid & 31, warp = tid >> 5;

    const size_t qbase = (size_t)b * CS * NQKV + (size_t)h * CDK;
    const size_t obase = (size_t)b * CS * CD   + (size_t)h * CDK;

    auto load_tile = [&](uint32_t dst, const __nv_bfloat16* src, size_t base, int tile) {
        const __nv_bfloat16* g = src + base + (size_t)tile * 64 * NQKV;
        #pragma unroll
        for (int i = 0; i < 4; ++i) {
            int id = tid + i * 128;
            int r = id >> 3, c = id & 7;
            cp16(dst + (uint32_t)r * 128u + (uint32_t)((c ^ (r & 7)) << 4),
                 g + (size_t)r * NQKV + c * 8);
        }
    };
    auto load_kv = [&](int kt) {
        uint32_t s = sb + 16384u + (uint32_t)(kt & 1) * 32768u;
        load_tile(s,          QKVh, qbase + 1024, kt);
        load_tile(s + 8192u,  QKVl, qbase + 1024, kt);
        load_tile(s + 16384u, QKVh, qbase + 2048, kt);
        load_tile(s + 24576u, QKVl, qbase + 2048, kt);
        asm volatile("cp.async.commit_group;" ::: "memory");
    };

    load_tile(QHs, QKVh, qbase, qt);
    load_tile(QLs, QKVl, qbase, qt);
    load_kv(0);
    cpwait<0>(); __syncthreads();

    uint32_t qfh[4][4], qfl[4][4];
    {
        int r = warp * 16 + (lane & 15);
        uint32_t ro = (uint32_t)r * 128u;
        int key = r & 7;
        #pragma unroll
        for (int ks = 0; ks < 4; ++ks) {
            uint32_t off = ro + (uint32_t)(((ks * 2 + (lane >> 4)) ^ key) << 4);
            ldsm4(qfh[ks], QHs + off);
            ldsm4(qfl[ks], QLs + off);
        }
    }

    float m0 = -1e30f, m1 = -1e30f, l0 = 0.f, l1 = 0.f;
    float oacc[8][4];
    #pragma unroll
    for (int nt = 0; nt < 8; ++nt)
        #pragma unroll
        for (int r = 0; r < 4; ++r) oacc[nt][r] = 0.f;

    const float c1 = 0.18033688011112042f;
    const int r0t = warp * 16 + (lane >> 2);

    for (int kt = 0; kt <= qt; ++kt) {
        if (kt + 1 <= qt) load_kv(kt + 1);
        if (kt > 0) {
            if (kt + 1 <= qt) cpwait<1>(); else cpwait<0>();
            __syncthreads();
        }
        const uint32_t KB  = sb + 16384u + (uint32_t)(kt & 1) * 32768u;
        const uint32_t KLB = KB + 8192u;
        const uint32_t VHB = KB + 16384u;
        const uint32_t VLB = KB + 24576u;

        float sacc[8][4];
        #pragma unroll
        for (int nt = 0; nt < 8; ++nt)
            #pragma unroll
            for (int r = 0; r < 4; ++r) sacc[nt][r] = 0.f;

        #pragma unroll
        for (int ks = 0; ks < 4; ++ks) {
            uint32_t bf[4][4];
            #pragma unroll
            for (int np = 0; np < 4; ++np) {
                int rr = np * 16 + (lane & 7) + ((lane >> 4) & 1) * 8;
                uint32_t chunk = (uint32_t)(ks * 2 + ((lane >> 3) & 1));
                ldsm4(bf[np], KB + (uint32_t)rr * 128u + ((chunk ^ (uint32_t)(rr & 7)) << 4));
            }
            #pragma unroll
            for (int nt = 0; nt < 8; ++nt) {
                mma16816(sacc[nt], qfh[ks], &bf[nt >> 1][(nt & 1) * 2]);
                mma16816(sacc[nt], qfl[ks], &bf[nt >> 1][(nt & 1) * 2]);
            }
        }
        #pragma unroll
        for (int ks = 0; ks < 4; ++ks) {
            uint32_t bf[4][4];
            #pragma unroll
            for (int np = 0; np < 4; ++np) {
                int rr = np * 16 + (lane & 7) + ((lane >> 4) & 1) * 8;
                uint32_t chunk = (uint32_t)(ks * 2 + ((lane >> 3) & 1));
                ldsm4(bf[np], KLB + (uint32_t)rr * 128u + ((chunk ^ (uint32_t)(rr & 7)) << 4));
            }
            #pragma unroll
            for (int nt = 0; nt < 8; ++nt)
                mma16816(sacc[nt], qfh[ks], &bf[nt >> 1][(nt & 1) * 2]);
        }

        const bool diag = (kt == qt);
        float rm0 = -1e30f, rm1 = -1e30f;
        #pragma unroll
        for (int nt = 0; nt < 8; ++nt) {
            const int cb = nt * 8 + 2 * (lane & 3);
            #pragma unroll
            for (int j = 0; j < 2; ++j) {
                float v = sacc[nt][j] * c1;
                if (diag && cb + j > r0t) v = -1e30f;
                sacc[nt][j] = v; rm0 = fmaxf(rm0, v);
                float w = sacc[nt][2 + j] * c1;
                if (diag && cb + j > r0t + 8) w = -1e30f;
                sacc[nt][2 + j] = w; rm1 = fmaxf(rm1, w);
            }
        }
        rm0 = fmaxf(rm0, __shfl_xor_sync(0xffffffffu, rm0, 1));
        rm0 = fmaxf(rm0, __shfl_xor_sync(0xffffffffu, rm0, 2));
        rm1 = fmaxf(rm1, __shfl_xor_sync(0xffffffffu, rm1, 1));
        rm1 = fmaxf(rm1, __shfl_xor_sync(0xffffffffu, rm1, 2));
        const float mn0 = fmaxf(m0, rm0), mn1 = fmaxf(m1, rm1);
        const float corr0 = ex2f(m0 - mn0), corr1 = ex2f(m1 - mn1);
        m0 = mn0; m1 = mn1;

        float ps0 = 0.f, ps1 = 0.f;
        uint32_t pfh[4][4], pfl[4][4];
        #pragma unroll
        for (int nt = 0; nt < 8; ++nt) {
            float p0 = ex2f(sacc[nt][0] - m0);
            float p1 = ex2f(sacc[nt][1] - m0);
            float p2 = ex2f(sacc[nt][2] - m1);
            float p3 = ex2f(sacc[nt][3] - m1);
            ps0 += p0 + p1; ps1 += p2 + p3;
            float h0 = __bfloat162float(__float2bfloat16(p0));
            float h1 = __bfloat162float(__float2bfloat16(p1));
            float h2 = __bfloat162float(__float2bfloat16(p2));
            float h3 = __bfloat162float(__float2bfloat16(p3));
            const int kc = nt >> 1, base = (nt & 1) * 2;
            pfh[kc][base]     = pack_bf2(h0, h1);
            pfh[kc][base + 1] = pack_bf2(h2, h3);
            pfl[kc][base]     = pack_bf2(p0 - h0, p1 - h1);
            pfl[kc][base + 1] = pack_bf2(p2 - h2, p3 - h3);
        }
        ps0 += __shfl_xor_sync(0xffffffffu, ps0, 1);
        ps0 += __shfl_xor_sync(0xffffffffu, ps0, 2);
        ps1 += __shfl_xor_sync(0xffffffffu, ps1, 1);
        ps1 += __shfl_xor_sync(0xffffffffu, ps1, 2);
        l0 = l0 * corr0 + ps0;
        l1 = l1 * corr1 + ps1;

        #pragma unroll
        for (int nt = 0; nt < 8; ++nt) {
            oacc[nt][0] *= corr0; oacc[nt][1] *= corr0;
            oacc[nt][2] *= corr1; oacc[nt][3] *= corr1;
        }

        const int vj  = lane >> 3, vlp = lane & 7;
        #pragma unroll
        for (int kc = 0; kc < 4; ++kc) {
            const int vrow = kc * 16 + (vj & 1) * 8 + vlp;
            const uint32_t vro = (uint32_t)vrow * 128u;
            const uint32_t vkey = (uint32_t)(vrow & 7);
            uint32_t vfh[4][4];
            #pragma unroll
            for (int vb = 0; vb < 4; ++vb) {
                uint32_t chunk = (uint32_t)(vb * 2 + (vj >> 1));
                ldsm4t(vfh[vb], VHB + vro + ((chunk ^ vkey) << 4));
            }
            #pragma unroll
            for (int nt = 0; nt < 8; ++nt) {
                mma16816(oacc[nt], pfh[kc], &vfh[nt >> 1][(nt & 1) * 2]);
                mma16816(oacc[nt], pfl[kc], &vfh[nt >> 1][(nt & 1) * 2]);
            }
            uint32_t vfl[4][4];
            #pragma unroll
            for (int vb = 0; vb < 4; ++vb) {
                uint32_t chunk = (uint32_t)(vb * 2 + (vj >> 1));
                ldsm4t(vfl[vb], VLB + vro + ((chunk ^ vkey) << 4));
            }
            #pragma unroll
            for (int nt = 0; nt < 8; ++nt)
                mma16816(oacc[nt], pfh[kc], &vfl[nt >> 1][(nt & 1) * 2]);
        }
        __syncthreads();
    }

    const float inv0 = 1.f / l0, inv1 = 1.f / l1;
    const size_t row0 = obase + (size_t)(qt * 64 + r0t) * CD;
    const size_t row1 = row0 + (size_t)8 * CD;
    #pragma unroll
    for (int nt = 0; nt < 8; ++nt) {
        const int cb = nt * 8 + 2 * (lane & 3);
        float v0 = oacc[nt][0] * inv0, v1 = oacc[nt][1] * inv0;
        float v2 = oacc[nt][2] * inv1, v3 = oacc[nt][3] * inv1;
        float h0 = __half2float(__float2half(v0));
        float h1 = __half2float(__float2half(v1));
        float h2 = __half2float(__float2half(v2));
        float h3 = __half2float(__float2half(v3));
        *reinterpret_cast<uint32_t*>(&Oh[row0 + cb]) = pack_hf2(h0, h1);
        *reinterpret_cast<uint32_t*>(&Oh[row1 + cb]) = pack_hf2(h2, h3);
        *reinterpret_cast<uint32_t*>(&Ol[row0 + cb]) = pack_hf2(v0 - h0, v1 - h1);
        *reinterpret_cast<uint32_t*>(&Ol[row1 + cb]) = pack_hf2(v2 - h2, v3 - h3);
    }
}

// ---------------- residual + LayerNorm (optional fp16 split outputs) ---------
__global__ __launch_bounds__(256)
void residual_ln(const float* __restrict__ x, const float* __restrict__ r,
                 const float* __restrict__ gamma, const float* __restrict__ beta,
                 float* __restrict__ out,
                 __half* __restrict__ outh, __half* __restrict__ outl)
{
    const int row = blockIdx.x;
    const int tid = threadIdx.x;
    const float4 a = reinterpret_cast<const float4*>(x + (size_t)row * CD)[tid];
    const float4 c = reinterpret_cast<const float4*>(r + (size_t)row * CD)[tid];
    float v0 = a.x + c.x, v1 = a.y + c.y, v2 = a.z + c.z, v3 = a.w + c.w;
    float s  = v0 + v1 + v2 + v3;
    float sq = v0 * v0 + v1 * v1 + v2 * v2 + v3 * v3;

    #pragma unroll
    for (int o = 16; o; o >>= 1) {
        s  += __shfl_xor_sync(0xffffffffu, s,  o);
        sq += __shfl_xor_sync(0xffffffffu, sq, o);
    }
    __shared__ float ss[8], sg[8];
    const int w = tid >> 5, lane = tid & 31;
    if (lane == 0) { ss[w] = s; sg[w] = sq; }
    __syncthreads();
    if (w == 0) {
        s  = (lane < 8) ? ss[lane] : 0.f;
        sq = (lane < 8) ? sg[lane] : 0.f;
        #pragma unroll
        for (int o = 4; o; o >>= 1) {
            s  += __shfl_xor_sync(0xffffffffu, s,  o);
            sq += __shfl_xor_sync(0xffffffffu, sq, o);
        }
        if (lane == 0) { ss[0] = s; sg[0] = sq; }
    }
    __syncthreads();
    s = ss[0]; sq = sg[0];

    const float mu  = s * (1.f / CD);
    const float var = sq * (1.f / CD) - mu * mu;
    const float inv = rsqrtf(var + 1e-5f);

    const float4 gv = reinterpret_cast<const float4*>(gamma)[tid];
    const float4 bv = reinterpret_cast<const float4*>(beta)[tid];
    float4 o4;
    o4.x = (v0 - mu) * inv * gv.x + bv.x;
    o4.y = (v1 - mu) * inv * gv.y + bv.y;
    o4.z = (v2 - mu) * inv * gv.z + bv.z;
    o4.w = (v3 - mu) * inv * gv.w + bv.w;
    reinterpret_cast<float4*>(out + (size_t)row * CD)[tid] = o4;

    if (outh) {
        __half2 h0, h1, lo0, lo1;
        h0.x = __float2half(o4.x); h0.y = __float2half(o4.y);
        h1.x = __float2half(o4.z); h1.y = __float2half(o4.w);
        lo0.x = __float2half(o4.x - __half2float(h0.x));
        lo0.y = __float2half(o4.y - __half2float(h0.y));
        lo1.x = __float2half(o4.z - __half2float(h1.x));
        lo1.y = __float2half(o4.w - __half2float(h1.y));
        reinterpret_cast<__half2*>(outh + (size_t)row * CD)[2*tid]   = h0;
        reinterpret_cast<__half2*>(outh + (size_t)row * CD)[2*tid+1] = h1;
        reinterpret_cast<__half2*>(outl + (size_t)row * CD)[2*tid]   = lo0;
        reinterpret_cast<__half2*>(outl + (size_t)row * CD)[2*tid+1] = lo1;
    }
}

// ---------------- launch -----------------------------------------------------
extern "C" void kernel_launch(void* const* d_in, const int* in_sizes, int n_in,
                              void* d_out, int out_size)
{
    const float* x  = (const float*)d_in[0];
    const float* Wq = (const float*)d_in[2];
    const float* bq = (const float*)d_in[3];
    const float* Wk = (const float*)d_in[4];
    const float* bk = (const float*)d_in[5];
    const float* Wv = (const float*)d_in[6];
    const float* bv = (const float*)d_in[7];
    const float* Wo = (const float*)d_in[8];
    const float* bo = (const float*)d_in[9];
    const float* g1 = (const float*)d_in[10];
    const float* b1 = (const float*)d_in[11];
    const float* W1 = (const float*)d_in[12];
    const float* c1 = (const float*)d_in[13];
    const float* W2 = (const float*)d_in[14];
    const float* c2 = (const float*)d_in[15];
    const float* g2 = (const float*)d_in[16];
    const float* b2 = (const float*)d_in[17];
    float* out = (float*)d_out;

    float *pr, *x1, *ff, *bqkv;
    cudaGetSymbolAddress((void**)&pr, g_pr);
    cudaGetSymbolAddress((void**)&x1, g_x1);
    cudaGetSymbolAddress((void**)&ff, g_ff);
    cudaGetSymbolAddress((void**)&bqkv, g_bqkv);

    __nv_bfloat16 *xh,*xl,*qkvh,*qkvl,*wqkvh,*wqkvl;
    cudaGetSymbolAddress((void**)&xh,   g_xh);   cudaGetSymbolAddress((void**)&xl,   g_xl);
    cudaGetSymbolAddress((void**)&qkvh, g_qkvh); cudaGetSymbolAddress((void**)&qkvl, g_qkvl);
    cudaGetSymbolAddress((void**)&wqkvh, g_wqkv_h); cudaGetSymbolAddress((void**)&wqkvl, g_wqkv_l);

    __half *aoh,*aol,*x1h,*x1l,*hhh,*hhl,*wo,*w1,*w2;
    cudaGetSymbolAddress((void**)&aoh, g_aoh); cudaGetSymbolAddress((void**)&aol, g_aol);
    cudaGetSymbolAddress((void**)&x1h, g_x1h); cudaGetSymbolAddress((void**)&x1l, g_x1l);
    cudaGetSymbolAddress((void**)&hhh, g_hhh); cudaGetSymbolAddress((void**)&hhl, g_hhl);
    cudaGetSymbolAddress((void**)&wo,  g_wo);
    cudaGetSymbolAddress((void**)&w1,  g_w1);
    cudaGetSymbolAddress((void**)&w2,  g_w2);

    cudaFuncSetAttribute(flash_hmma, cudaFuncAttributeMaxDynamicSharedMemorySize, FA_SMEM);
    cudaFuncSetAttribute(hgemm_bf16x3, cudaFuncAttributeMaxDynamicSharedMemorySize, HG_SMEM);
    cudaFuncSetAttribute(hgemm_fp16x2<0>, cudaFuncAttributeMaxDynamicSharedMemorySize, HF_SMEM);
    cudaFuncSetAttribute(hgemm_fp16x2<2>, cudaFuncAttributeMaxDynamicSharedMemorySize, HF_SMEM);

    prep_all<<<20481, 256>>>(x, Wq, Wk, Wv, Wo, W1, W2, bq, bk, bv);

    dim3 gQKV(NQKV / 128, MTOT / 128);
    dim3 gD(CD / 128, MTOT / 128);
    dim3 gF(CF / 128, MTOT / 128);

    hgemm_bf16x3<<<gQKV, 128, HG_SMEM>>>(xh, xl, wqkvh, wqkvl, bqkv,
                                         qkvh, qkvl, MTOT, NQKV, CD);

    flash_hmma<<<dim3(CS / 64, CB * CH), 128, FA_SMEM>>>(qkvh, qkvl, aoh, aol);

    hgemm_fp16x2<0><<<gD, 128, HF_SMEM>>>(aoh, aol, wo, bo, pr, nullptr, nullptr, MTOT, CD, CD);
    residual_ln<<<MTOT, 256>>>(x, pr, g1, b1, x1, x1h, x1l);

    hgemm_fp16x2<2><<<gF, 128, HF_SMEM>>>(x1h, x1l, w1, c1, nullptr, hhh, hhl, MTOT, CF, CD);
    hgemm_fp16x2<0><<<gD, 128, HF_SMEM>>>(hhh, hhl, w2, c2, ff, nullptr, nullptr, MTOT, CD, CF);
    residual_ln<<<MTOT, 256>>>(x1, ff, g2, b2, out, nullptr, nullptr);
}

// round 11
// speedup vs baseline: 1.3993x; 1.1580x over previous
#include <cuda_runtime.h>
#include <cuda_fp16.h>
#include <stdint.h>
#include <math.h>

#define CB 4
#define CS 2048
#define CD 1024
#define CH 16
#define CDK 64
#define CF 4096
#define MTOT (CB*CS)   // 8192
#define NQKV 3072

#define HF_SMEM (4 * 24576)       // fp16x2 gemm: 4 stages x 24KB = 96KB -> 2 CTA/SM
#define FA_SMEM 49152             // flash: Qh/Ql 16KB + 2 KV stages x 16KB

// ---------------- scratch (device globals; no allocations allowed) ----------
__device__ float g_pr[(size_t)MTOT*CD];
__device__ float g_x1[(size_t)MTOT*CD];
__device__ float g_ff[(size_t)MTOT*CD];

__device__ __half g_xh  [(size_t)MTOT*CD],  g_xl  [(size_t)MTOT*CD];
__device__ __half g_qkvh[(size_t)MTOT*NQKV], g_qkvl[(size_t)MTOT*NQKV];
__device__ __half g_aoh [(size_t)MTOT*CD],  g_aol [(size_t)MTOT*CD];
__device__ __half g_x1h [(size_t)MTOT*CD],  g_x1l [(size_t)MTOT*CD];
__device__ __half g_hhh [(size_t)MTOT*CF],  g_hhl [(size_t)MTOT*CF];

__device__ __half g_wqkv[(size_t)NQKV*CD];
__device__ __half g_wo[(size_t)CD*CD];
__device__ __half g_w1[(size_t)CF*CD];
__device__ __half g_w2[(size_t)CD*CF];
__device__ float g_bqkv[NQKV];

// ---------------- PTX helpers (non-'a' features only) ------------------------
__device__ __forceinline__ uint32_t smem_u32(const void* p) {
    uint32_t a;
    asm("{ .reg .u64 t; cvta.to.shared.u64 t, %1; cvt.u32.u64 %0, t; }" : "=r"(a) : "l"(p));
    return a;
}
__device__ __forceinline__ void cp16(uint32_t dst, const void* src) {
    asm volatile("cp.async.cg.shared.global [%0], [%1], 16;" :: "r"(dst), "l"(src));
}
template<int N> __device__ __forceinline__ void cpwait() {
    asm volatile("cp.async.wait_group %0;" :: "n"(N) : "memory");
}
__device__ __forceinline__ void ldsm4(uint32_t* r, uint32_t addr) {
    asm volatile("ldmatrix.sync.aligned.m8n8.x4.shared.b16 {%0,%1,%2,%3}, [%4];"
                 : "=r"(r[0]), "=r"(r[1]), "=r"(r[2]), "=r"(r[3]) : "r"(addr));
}
__device__ __forceinline__ void ldsm4t(uint32_t* r, uint32_t addr) {
    asm volatile("ldmatrix.sync.aligned.m8n8.x4.trans.shared.b16 {%0,%1,%2,%3}, [%4];"
                 : "=r"(r[0]), "=r"(r[1]), "=r"(r[2]), "=r"(r[3]) : "r"(addr));
}
__device__ __forceinline__ void mma16816h(float* c, const uint32_t* a, const uint32_t* b) {
    asm volatile(
        "mma.sync.aligned.m16n8k16.row.col.f32.f16.f16.f32 "
        "{%0,%1,%2,%3}, {%4,%5,%6,%7}, {%8,%9}, {%0,%1,%2,%3};"
        : "+f"(c[0]), "+f"(c[1]), "+f"(c[2]), "+f"(c[3])
        : "r"(a[0]), "r"(a[1]), "r"(a[2]), "r"(a[3]), "r"(b[0]), "r"(b[1]));
}
__device__ __forceinline__ float ex2f(float x) {
    float y; asm("ex2.approx.ftz.f32 %0, %1;" : "=f"(y) : "f"(x)); return y;
}
__device__ __forceinline__ uint32_t pack_hf2(float a, float b) {
    __half2 h; h.x = __float2half(a); h.y = __float2half(b);
    return *reinterpret_cast<uint32_t*>(&h);
}

// ---------------- mega prep kernel -------------------------------------------
// blocks [0,8192): split x (fp16 hi/lo). [8192,20480): weight fp16 transposes.
// [20480]: bias concat.
__global__ __launch_bounds__(256)
void prep_all(const float* __restrict__ x,
              const float* __restrict__ Wq, const float* __restrict__ Wk,
              const float* __restrict__ Wv, const float* __restrict__ Wo,
              const float* __restrict__ W1, const float* __restrict__ W2,
              const float* __restrict__ bq, const float* __restrict__ bk,
              const float* __restrict__ bv)
{
    __shared__ float t[32][33];
    const int blk = blockIdx.x;
    const int tid = threadIdx.x;

    if (blk < 8192) {                       // ---- split x (fp16 hi/lo)
        int i = blk * 256 + tid;
        float4 v = reinterpret_cast<const float4*>(x)[i];
        __half h0 = __float2half(v.x), h1 = __float2half(v.y);
        __half h2 = __float2half(v.z), h3 = __float2half(v.w);
        __half2 a, b;
        a.x = h0; a.y = h1; b.x = h2; b.y = h3;
        reinterpret_cast<__half2*>(g_xh)[2*i]   = a;
        reinterpret_cast<__half2*>(g_xh)[2*i+1] = b;
        a.x = __float2half(v.x - __half2float(h0));
        a.y = __float2half(v.y - __half2float(h1));
        b.x = __float2half(v.z - __half2float(h2));
        b.y = __float2half(v.w - __half2float(h3));
        reinterpret_cast<__half2*>(g_xl)[2*i]   = a;
        reinterpret_cast<__half2*>(g_xl)[2*i+1] = b;
        return;
    }
    if (blk == 20480) {                     // ---- bias concat
        for (int i = tid; i < NQKV; i += 256)
            g_bqkv[i] = (i < 1024) ? bq[i] : (i < 2048) ? bk[i-1024] : bv[i-2048];
        return;
    }

    int b = blk - 8192;
    const float* W; __half* hT; int Kd, Nd;
    if      (b < 1024)  { W = Wq; hT = g_wqkv;              Kd = CD; Nd = CD; }
    else if (b < 2048)  { W = Wk; hT = g_wqkv + 1024u*CD;   Kd = CD; Nd = CD; b -= 1024; }
    else if (b < 3072)  { W = Wv; hT = g_wqkv + 2048u*CD;   Kd = CD; Nd = CD; b -= 2048; }
    else if (b < 4096)  { W = Wo; hT = g_wo; Kd = CD; Nd = CD; b -= 3072; }
    else if (b < 8192)  { W = W1; hT = g_w1; Kd = CD; Nd = CF; b -= 4096; }
    else                { W = W2; hT = g_w2; Kd = CF; Nd = CD; b -= 8192; }

    const int nb = Nd / 32;
    const int n0 = (b % nb) * 32, k0 = (b / nb) * 32;
    const int tx = tid & 31, ty = tid >> 5;
    for (int i = ty; i < 32; i += 8)
        t[i][tx] = W[(size_t)(k0 + i) * Nd + n0 + tx];
    __syncthreads();
    for (int i = ty; i < 32; i += 8)
        hT[(size_t)(n0 + i) * Kd + k0 + tx] = __float2half(t[tx][i]);
}

// ---------------- HMMA fp16x2 GEMM -------------------------------------------
// C = (Ah+Al)[M,K] @ B[N,K]^T + bias, A fp16 hi/lo, B single fp16.
// 128 thr, 4 warps, 64x64 warp tiles, 4-stage ring (96KB, 2 CTA/SM).
// EPI: 0 = fp32 C, 1 = fp16 hi/lo split, 2 = relu + fp16 hi/lo split
template<int EPI>
__global__ __launch_bounds__(128, 2)
void hgemm_fp16x2(const __half* __restrict__ Ah, const __half* __restrict__ Al,
                  const __half* __restrict__ B,
                  const float* __restrict__ bias, float* __restrict__ C,
                  __half* __restrict__ Chi, __half* __restrict__ Clo,
                  int M, int N, int K)
{
    extern __shared__ __align__(1024) char smraw[];
    const uint32_t sbase = smem_u32(smraw);

    const int tid  = threadIdx.x;
    const int lane = tid & 31;
    const int wid  = tid >> 5;
    const int warp_m = wid & 1;
    const int warp_n = wid >> 1;
    const int brow = blockIdx.y, bcol = blockIdx.x;

    const int lr = tid >> 2;
    const int lc = tid & 3;
    const int KC = K >> 5;

    uint32_t swr[4];
    size_t agr[4], bgr[4];
    #pragma unroll
    for (int rr = 0; rr < 4; ++rr) {
        int r = lr + rr * 32;
        int key = (r >> 1) & 3;
        swr[rr] = (uint32_t)r * 64u + (uint32_t)((lc ^ key) << 4);
        agr[rr] = (size_t)(brow * 128 + r) * (size_t)K;
        bgr[rr] = (size_t)(bcol * 128 + r) * (size_t)K;
    }

    uint32_t a_rb[4]; int a_key[4];
    #pragma unroll
    for (int mt = 0; mt < 4; ++mt) {
        int r = warp_m * 64 + mt * 16 + (lane & 15);
        a_rb[mt] = (uint32_t)r * 64u;
        a_key[mt] = (r >> 1) & 3;
    }
    const int a_ch = lane >> 4;
    uint32_t b_rb[4]; int b_key[4];
    #pragma unroll
    for (int np = 0; np < 4; ++np) {
        int r = warp_n * 64 + np * 16 + (lane & 7) + ((lane >> 4) & 1) * 8;
        b_rb[np] = (uint32_t)r * 64u;
        b_key[np] = (r >> 1) & 3;
    }
    const int b_ch = (lane >> 3) & 1;

    float acc[4][8][4];
    #pragma unroll
    for (int mt = 0; mt < 4; ++mt)
        #pragma unroll
        for (int nt = 0; nt < 8; ++nt)
            #pragma unroll
            for (int r = 0; r < 4; ++r) acc[mt][nt][r] = 0.f;

    // stage = Ah(8KB) | Al(8KB) | B(8KB)
    auto load_stage = [&](int kk, int s) {
        const size_t ko = (size_t)kk * 32 + (size_t)lc * 8;
        const uint32_t st = sbase + (uint32_t)s * 24576u;
        #pragma unroll
        for (int rr = 0; rr < 4; ++rr) {
            cp16(st +          swr[rr], Ah + agr[rr] + ko);
            cp16(st +  8192u + swr[rr], Al + agr[rr] + ko);
            cp16(st + 16384u + swr[rr], B  + bgr[rr] + ko);
        }
        asm volatile("cp.async.commit_group;" ::: "memory");
    };

    load_stage(0, 0);
    if (KC > 1) load_stage(1, 1);
    if (KC > 2) load_stage(2, 2);

    for (int t = 0; t < KC; ++t) {
        if (t + 2 < KC) cpwait<2>(); else if (t + 1 < KC) cpwait<1>(); else cpwait<0>();
        __syncthreads();
        if (t + 3 < KC) load_stage(t + 3, (t + 3) & 3);

        const uint32_t st = sbase + (uint32_t)(t & 3) * 24576u;
        #pragma unroll
        for (int ks = 0; ks < 2; ++ks) {
            uint32_t bf[4][4];
            #pragma unroll
            for (int np = 0; np < 4; ++np)
                ldsm4(bf[np], st + 16384u + b_rb[np] +
                      (uint32_t)((((ks << 1) + b_ch) ^ b_key[np]) << 4));
            uint32_t ah[4][4];
            #pragma unroll
            for (int mt = 0; mt < 4; ++mt)
                ldsm4(ah[mt], st + a_rb[mt] +
                      (uint32_t)((((ks << 1) + a_ch) ^ a_key[mt]) << 4));
            #pragma unroll
            for (int mt = 0; mt < 4; ++mt)
                #pragma unroll
                for (int nt = 0; nt < 8; ++nt)
                    mma16816h(acc[mt][nt], ah[mt], &bf[nt >> 1][(nt & 1) * 2]);
            {
                uint32_t al[4][4];
                #pragma unroll
                for (int mt = 0; mt < 4; ++mt)
                    ldsm4(al[mt], st + 8192u + a_rb[mt] +
                          (uint32_t)((((ks << 1) + a_ch) ^ a_key[mt]) << 4));
                #pragma unroll
                for (int mt = 0; mt < 4; ++mt)
                    #pragma unroll
                    for (int nt = 0; nt < 8; ++nt)
                        mma16816h(acc[mt][nt], al[mt], &bf[nt >> 1][(nt & 1) * 2]);
            }
        }
    }

    const int ng_base = bcol * 128 + warp_n * 64 + (lane & 3) * 2;
    const int mg_base = brow * 128 + warp_m * 64 + (lane >> 2);
    #pragma unroll
    for (int nt = 0; nt < 8; ++nt) {
        const int n = ng_base + nt * 8;
        const float2 bb = *reinterpret_cast<const float2*>(&bias[n]);
        #pragma unroll
        for (int mt = 0; mt < 4; ++mt) {
            const int m0 = mg_base + mt * 16;
            float v0 = acc[mt][nt][0] + bb.x, v1 = acc[mt][nt][1] + bb.y;
            float v2 = acc[mt][nt][2] + bb.x, v3 = acc[mt][nt][3] + bb.y;
            if (EPI == 2) {
                v0 = fmaxf(v0, 0.f); v1 = fmaxf(v1, 0.f);
                v2 = fmaxf(v2, 0.f); v3 = fmaxf(v3, 0.f);
            }
            if (EPI == 0) {
                float2 o0{v0, v1}, o1{v2, v3};
                *reinterpret_cast<float2*>(&C[(size_t)m0 * N + n])       = o0;
                *reinterpret_cast<float2*>(&C[(size_t)(m0 + 8) * N + n]) = o1;
            } else {
                __half2 h0, h1, l0, l1;
                h0.x = __float2half(v0); h0.y = __float2half(v1);
                h1.x = __float2half(v2); h1.y = __float2half(v3);
                l0.x = __float2half(v0 - __half2float(h0.x));
                l0.y = __float2half(v1 - __half2float(h0.y));
                l1.x = __float2half(v2 - __half2float(h1.x));
                l1.y = __float2half(v3 - __half2float(h1.y));
                *reinterpret_cast<__half2*>(&Chi[(size_t)m0 * N + n])       = h0;
                *reinterpret_cast<__half2*>(&Chi[(size_t)(m0 + 8) * N + n]) = h1;
                *reinterpret_cast<__half2*>(&Clo[(size_t)m0 * N + n])       = l0;
                *reinterpret_cast<__half2*>(&Clo[(size_t)(m0 + 8) * N + n]) = l1;
            }
        }
    }
}

// ---------------- Flash attention, fp16 2-pass (causal) ----------------------
// S = (Qh+Ql)·Kh, O += (Ph+Pl)·Vh.  K,V single fp16; KV stage = 16KB.
__global__ __launch_bounds__(128)
void flash_hmma(const __half* __restrict__ QKVh, const __half* __restrict__ QKVl,
                __half* __restrict__ Oh, __half* __restrict__ Ol)
{
    extern __shared__ __align__(1024) char smraw[];
    const uint32_t sb = smem_u32(smraw);
    const uint32_t QHs = sb, QLs = sb + 8192;

    const int qt = (int)gridDim.x - 1 - (int)blockIdx.x;
    const int b  = blockIdx.y >> 4, h = blockIdx.y & 15;
    const int tid = threadIdx.x, lane = tid & 31, warp = tid >> 5;

    const size_t qbase = (size_t)b * CS * NQKV + (size_t)h * CDK;
    const size_t obase = (size_t)b * CS * CD   + (size_t)h * CDK;

    auto load_tile = [&](uint32_t dst, const __half* src, size_t base, int tile) {
        const __half* g = src + base + (size_t)tile * 64 * NQKV;
        #pragma unroll
        for (int i = 0; i < 4; ++i) {
            int id = tid + i * 128;
            int r = id >> 3, c = id & 7;
            cp16(dst + (uint32_t)r * 128u + (uint32_t)((c ^ (r & 7)) << 4),
                 g + (size_t)r * NQKV + c * 8);
        }
    };
    auto load_kv = [&](int kt) {
        uint32_t s = sb + 16384u + (uint32_t)(kt & 1) * 16384u;
        load_tile(s,         QKVh, qbase + 1024, kt);   // Kh
        load_tile(s + 8192u, QKVh, qbase + 2048, kt);   // Vh
        asm volatile("cp.async.commit_group;" ::: "memory");
    };

    load_tile(QHs, QKVh, qbase, qt);
    load_tile(QLs, QKVl, qbase, qt);
    load_kv(0);
    cpwait<0>(); __syncthreads();

    uint32_t qfh[4][4], qfl[4][4];
    {
        int r = warp * 16 + (lane & 15);
        uint32_t ro = (uint32_t)r * 128u;
        int key = r & 7;
        #pragma unroll
        for (int ks = 0; ks < 4; ++ks) {
            uint32_t off = ro + (uint32_t)(((ks * 2 + (lane >> 4)) ^ key) << 4);
            ldsm4(qfh[ks], QHs + off);
            ldsm4(qfl[ks], QLs + off);
        }
    }

    float m0 = -1e30f, m1 = -1e30f, l0 = 0.f, l1 = 0.f;
    float oacc[8][4];
    #pragma unroll
    for (int nt = 0; nt < 8; ++nt)
        #pragma unroll
        for (int r = 0; r < 4; ++r) oacc[nt][r] = 0.f;

    const float c1 = 0.18033688011112042f;
    const int r0t = warp * 16 + (lane >> 2);

    for (int kt = 0; kt <= qt; ++kt) {
        if (kt + 1 <= qt) load_kv(kt + 1);
        if (kt > 0) {
            if (kt + 1 <= qt) cpwait<1>(); else cpwait<0>();
            __syncthreads();
        }
        const uint32_t KB  = sb + 16384u + (uint32_t)(kt & 1) * 16384u;
        const uint32_t VHB = KB + 8192u;

        float sacc[8][4];
        #pragma unroll
        for (int nt = 0; nt < 8; ++nt)
            #pragma unroll
            for (int r = 0; r < 4; ++r) sacc[nt][r] = 0.f;

        #pragma unroll
        for (int ks = 0; ks < 4; ++ks) {
            uint32_t bf[4][4];
            #pragma unroll
            for (int np = 0; np < 4; ++np) {
                int rr = np * 16 + (lane & 7) + ((lane >> 4) & 1) * 8;
                uint32_t chunk = (uint32_t)(ks * 2 + ((lane >> 3) & 1));
                ldsm4(bf[np], KB + (uint32_t)rr * 128u + ((chunk ^ (uint32_t)(rr & 7)) << 4));
            }
            #pragma unroll
            for (int nt = 0; nt < 8; ++nt) {
                mma16816h(sacc[nt], qfh[ks], &bf[nt >> 1][(nt & 1) * 2]);
                mma16816h(sacc[nt], qfl[ks], &bf[nt >> 1][(nt & 1) * 2]);
            }
        }

        const bool diag = (kt == qt);
        float rm0 = -1e30f, rm1 = -1e30f;
        #pragma unroll
        for (int nt = 0; nt < 8; ++nt) {
            const int cb = nt * 8 + 2 * (lane & 3);
            #pragma unroll
            for (int j = 0; j < 2; ++j) {
                float v = sacc[nt][j] * c1;
                if (diag && cb + j > r0t) v = -1e30f;
                sacc[nt][j] = v; rm0 = fmaxf(rm0, v);
                float w = sacc[nt][2 + j] * c1;
                if (diag && cb + j > r0t + 8) w = -1e30f;
                sacc[nt][2 + j] = w; rm1 = fmaxf(rm1, w);
            }
        }
        rm0 = fmaxf(rm0, __shfl_xor_sync(0xffffffffu, rm0, 1));
        rm0 = fmaxf(rm0, __shfl_xor_sync(0xffffffffu, rm0, 2));
        rm1 = fmaxf(rm1, __shfl_xor_sync(0xffffffffu, rm1, 1));
        rm1 = fmaxf(rm1, __shfl_xor_sync(0xffffffffu, rm1, 2));
        const float mn0 = fmaxf(m0, rm0), mn1 = fmaxf(m1, rm1);
        const float corr0 = ex2f(m0 - mn0), corr1 = ex2f(m1 - mn1);
        m0 = mn0; m1 = mn1;

        float ps0 = 0.f, ps1 = 0.f;
        uint32_t pfh[4][4], pfl[4][4];
        #pragma unroll
        for (int nt = 0; nt < 8; ++nt) {
            float p0 = ex2f(sacc[nt][0] - m0);
            float p1 = ex2f(sacc[nt][1] - m0);
            float p2 = ex2f(sacc[nt][2] - m1);
            float p3 = ex2f(sacc[nt][3] - m1);
            ps0 += p0 + p1; ps1 += p2 + p3;
            float h0 = __half2float(__float2half(p0));
            float h1 = __half2float(__float2half(p1));
            float h2 = __half2float(__float2half(p2));
            float h3 = __half2float(__float2half(p3));
            const int kc = nt >> 1, base = (nt & 1) * 2;
            pfh[kc][base]     = pack_hf2(h0, h1);
            pfh[kc][base + 1] = pack_hf2(h2, h3);
            pfl[kc][base]     = pack_hf2(p0 - h0, p1 - h1);
            pfl[kc][base + 1] = pack_hf2(p2 - h2, p3 - h3);
        }
        ps0 += __shfl_xor_sync(0xffffffffu, ps0, 1);
        ps0 += __shfl_xor_sync(0xffffffffu, ps0, 2);
        ps1 += __shfl_xor_sync(0xffffffffu, ps1, 1);
        ps1 += __shfl_xor_sync(0xffffffffu, ps1, 2);
        l0 = l0 * corr0 + ps0;
        l1 = l1 * corr1 + ps1;

        #pragma unroll
        for (int nt = 0; nt < 8; ++nt) {
            oacc[nt][0] *= corr0; oacc[nt][1] *= corr0;
            oacc[nt][2] *= corr1; oacc[nt][3] *= corr1;
        }

        const int vj  = lane >> 3, vlp = lane & 7;
        #pragma unroll
        for (int kc = 0; kc < 4; ++kc) {
            const int vrow = kc * 16 + (vj & 1) * 8 + vlp;
            const uint32_t vro = (uint32_t)vrow * 128u;
            const uint32_t vkey = (uint32_t)(vrow & 7);
            uint32_t vfh[4][4];
            #pragma unroll
            for (int vb = 0; vb < 4; ++vb) {
                uint32_t chunk = (uint32_t)(vb * 2 + (vj >> 1));
                ldsm4t(vfh[vb], VHB + vro + ((chunk ^ vkey) << 4));
            }
            #pragma unroll
            for (int nt = 0; nt < 8; ++nt) {
                mma16816h(oacc[nt], pfh[kc], &vfh[nt >> 1][(nt & 1) * 2]);
                mma16816h(oacc[nt], pfl[kc], &vfh[nt >> 1][(nt & 1) * 2]);
            }
        }
        __syncthreads();
    }

    const float inv0 = 1.f / l0, inv1 = 1.f / l1;
    const size_t row0 = obase + (size_t)(qt * 64 + r0t) * CD;
    const size_t row1 = row0 + (size_t)8 * CD;
    #pragma unroll
    for (int nt = 0; nt < 8; ++nt) {
        const int cb = nt * 8 + 2 * (lane & 3);
        float v0 = oacc[nt][0] * inv0, v1 = oacc[nt][1] * inv0;
        float v2 = oacc[nt][2] * inv1, v3 = oacc[nt][3] * inv1;
        float h0 = __half2float(__float2half(v0));
        float h1 = __half2float(__float2half(v1));
        float h2 = __half2float(__float2half(v2));
        float h3 = __half2float(__float2half(v3));
        *reinterpret_cast<uint32_t*>(&Oh[row0 + cb]) = pack_hf2(h0, h1);
        *reinterpret_cast<uint32_t*>(&Oh[row1 + cb]) = pack_hf2(h2, h3);
        *reinterpret_cast<uint32_t*>(&Ol[row0 + cb]) = pack_hf2(v0 - h0, v1 - h1);
        *reinterpret_cast<uint32_t*>(&Ol[row1 + cb]) = pack_hf2(v2 - h2, v3 - h3);
    }
}

// ---------------- residual + LayerNorm (optional fp16 split outputs) ---------
__global__ __launch_bounds__(256)
void residual_ln(const float* __restrict__ x, const float* __restrict__ r,
                 const float* __restrict__ gamma, const float* __restrict__ beta,
                 float* __restrict__ out,
                 __half* __restrict__ outh, __half* __restrict__ outl)
{
    const int row = blockIdx.x;
    const int tid = threadIdx.x;
    const float4 a = reinterpret_cast<const float4*>(x + (size_t)row * CD)[tid];
    const float4 c = reinterpret_cast<const float4*>(r + (size_t)row * CD)[tid];
    float v0 = a.x + c.x, v1 = a.y + c.y, v2 = a.z + c.z, v3 = a.w + c.w;
    float s  = v0 + v1 + v2 + v3;
    float sq = v0 * v0 + v1 * v1 + v2 * v2 + v3 * v3;

    #pragma unroll
    for (int o = 16; o; o >>= 1) {
        s  += __shfl_xor_sync(0xffffffffu, s,  o);
        sq += __shfl_xor_sync(0xffffffffu, sq, o);
    }
    __shared__ float ss[8], sg[8];
    const int w = tid >> 5, lane = tid & 31;
    if (lane == 0) { ss[w] = s; sg[w] = sq; }
    __syncthreads();
    if (w == 0) {
        s  = (lane < 8) ? ss[lane] : 0.f;
        sq = (lane < 8) ? sg[lane] : 0.f;
        #pragma unroll
        for (int o = 4; o; o >>= 1) {
            s  += __shfl_xor_sync(0xffffffffu, s,  o);
            sq += __shfl_xor_sync(0xffffffffu, sq, o);
        }
        if (lane == 0) { ss[0] = s; sg[0] = sq; }
    }
    __syncthreads();
    s = ss[0]; sq = sg[0];

    const float mu  = s * (1.f / CD);
    const float var = sq * (1.f / CD) - mu * mu;
    const float inv = rsqrtf(var + 1e-5f);

    const float4 gv = reinterpret_cast<const float4*>(gamma)[tid];
    const float4 bv = reinterpret_cast<const float4*>(beta)[tid];
    float4 o4;
    o4.x = (v0 - mu) * inv * gv.x + bv.x;
    o4.y = (v1 - mu) * inv * gv.y + bv.y;
    o4.z = (v2 - mu) * inv * gv.z + bv.z;
    o4.w = (v3 - mu) * inv * gv.w + bv.w;
    reinterpret_cast<float4*>(out + (size_t)row * CD)[tid] = o4;

    if (outh) {
        __half2 h0, h1, lo0, lo1;
        h0.x = __float2half(o4.x); h0.y = __float2half(o4.y);
        h1.x = __float2half(o4.z); h1.y = __float2half(o4.w);
        lo0.x = __float2half(o4.x - __half2float(h0.x));
        lo0.y = __float2half(o4.y - __half2float(h0.y));
        lo1.x = __float2half(o4.z - __half2float(h1.x));
        lo1.y = __float2half(o4.w - __half2float(h1.y));
        reinterpret_cast<__half2*>(outh + (size_t)row * CD)[2*tid]   = h0;
        reinterpret_cast<__half2*>(outh + (size_t)row * CD)[2*tid+1] = h1;
        reinterpret_cast<__half2*>(outl + (size_t)row * CD)[2*tid]   = lo0;
        reinterpret_cast<__half2*>(outl + (size_t)row * CD)[2*tid+1] = lo1;
    }
}

// ---------------- launch -----------------------------------------------------
extern "C" void kernel_launch(void* const* d_in, const int* in_sizes, int n_in,
                              void* d_out, int out_size)
{
    const float* x  = (const float*)d_in[0];
    const float* Wq = (const float*)d_in[2];
    const float* bq = (const float*)d_in[3];
    const float* Wk = (const float*)d_in[4];
    const float* bk = (const float*)d_in[5];
    const float* Wv = (const float*)d_in[6];
    const float* bv = (const float*)d_in[7];
    const float* Wo = (const float*)d_in[8];
    const float* bo = (const float*)d_in[9];
    const float* g1 = (const float*)d_in[10];
    const float* b1 = (const float*)d_in[11];
    const float* W1 = (const float*)d_in[12];
    const float* c1 = (const float*)d_in[13];
    const float* W2 = (const float*)d_in[14];
    const float* c2 = (const float*)d_in[15];
    const float* g2 = (const float*)d_in[16];
    const float* b2 = (const float*)d_in[17];
    float* out = (float*)d_out;

    float *pr, *x1, *ff, *bqkv;
    cudaGetSymbolAddress((void**)&pr, g_pr);
    cudaGetSymbolAddress((void**)&x1, g_x1);
    cudaGetSymbolAddress((void**)&ff, g_ff);
    cudaGetSymbolAddress((void**)&bqkv, g_bqkv);

    __half *xh,*xl,*qkvh,*qkvl,*aoh,*aol,*x1h,*x1l,*hhh,*hhl,*wqkv,*wo,*w1,*w2;
    cudaGetSymbolAddress((void**)&xh,   g_xh);   cudaGetSymbolAddress((void**)&xl,   g_xl);
    cudaGetSymbolAddress((void**)&qkvh, g_qkvh); cudaGetSymbolAddress((void**)&qkvl, g_qkvl);
    cudaGetSymbolAddress((void**)&aoh,  g_aoh);  cudaGetSymbolAddress((void**)&aol,  g_aol);
    cudaGetSymbolAddress((void**)&x1h,  g_x1h);  cudaGetSymbolAddress((void**)&x1l,  g_x1l);
    cudaGetSymbolAddress((void**)&hhh,  g_hhh);  cudaGetSymbolAddress((void**)&hhl,  g_hhl);
    cudaGetSymbolAddress((void**)&wqkv, g_wqkv);
    cudaGetSymbolAddress((void**)&wo,   g_wo);
    cudaGetSymbolAddress((void**)&w1,   g_w1);
    cudaGetSymbolAddress((void**)&w2,   g_w2);

    cudaFuncSetAttribute(flash_hmma, cudaFuncAttributeMaxDynamicSharedMemorySize, FA_SMEM);
    cudaFuncSetAttribute(hgemm_fp16x2<0>, cudaFuncAttributeMaxDynamicSharedMemorySize, HF_SMEM);
    cudaFuncSetAttribute(hgemm_fp16x2<1>, cudaFuncAttributeMaxDynamicSharedMemorySize, HF_SMEM);
    cudaFuncSetAttribute(hgemm_fp16x2<2>, cudaFuncAttributeMaxDynamicSharedMemorySize, HF_SMEM);

    prep_all<<<20481, 256>>>(x, Wq, Wk, Wv, Wo, W1, W2, bq, bk, bv);

    dim3 gQKV(NQKV / 128, MTOT / 128);
    dim3 gD(CD / 128, MTOT / 128);
    dim3 gF(CF / 128, MTOT / 128);

    hgemm_fp16x2<1><<<gQKV, 128, HF_SMEM>>>(xh, xl, wqkv, bqkv,
                                            nullptr, qkvh, qkvl, MTOT, NQKV, CD);

    flash_hmma<<<dim3(CS / 64, CB * CH), 128, FA_SMEM>>>(qkvh, qkvl, aoh, aol);

    hgemm_fp16x2<0><<<gD, 128, HF_SMEM>>>(aoh, aol, wo, bo, pr, nullptr, nullptr, MTOT, CD, CD);
    residual_ln<<<MTOT, 256>>>(x, pr, g1, b1, x1, x1h, x1l);

    hgemm_fp16x2<2><<<gF, 128, HF_SMEM>>>(x1h, x1l, w1, c1, nullptr, hhh, hhl, MTOT, CF, CD);
    hgemm_fp16x2<0><<<gD, 128, HF_SMEM>>>(hhh, hhl, w2, c2, ff, nullptr, nullptr, MTOT, CD, CF);
    residual_ln<<<MTOT, 256>>>(x1, ff, g2, b2, out, nullptr, nullptr);
}

// round 12
// speedup vs baseline: 2.6080x; 1.8637x over previous
#include <cuda_runtime.h>
#include <cuda_fp16.h>
#include <stdint.h>
#include <math.h>

#define CB 4
#define CS 2048
#define CD 1024
#define CH 16
#define CDK 64
#define CF 4096
#define MTOT (CB*CS)   // 8192
#define NQKV 3072

#define HF_SMEM (4 * 16384)       // fp16 gemm: 4 stages x (A 8KB + B 8KB) = 64KB
#define FA_SMEM 40960             // flash: Q 8KB + 2 KV stages x 16KB

// ---------------- scratch (device globals; no allocations allowed) ----------
__device__ float g_pr[(size_t)MTOT*CD];
__device__ float g_x1[(size_t)MTOT*CD];
__device__ float g_ff[(size_t)MTOT*CD];

__device__ __half g_x  [(size_t)MTOT*CD];
__device__ __half g_qkv[(size_t)MTOT*NQKV];
__device__ __half g_ao [(size_t)MTOT*CD];
__device__ __half g_x1h[(size_t)MTOT*CD];
__device__ __half g_hh [(size_t)MTOT*CF];

__device__ __half g_wqkv[(size_t)NQKV*CD];
__device__ __half g_wo[(size_t)CD*CD];
__device__ __half g_w1[(size_t)CF*CD];
__device__ __half g_w2[(size_t)CD*CF];
__device__ float g_bqkv[NQKV];

// ---------------- PTX helpers (non-'a' features only) ------------------------
__device__ __forceinline__ uint32_t smem_u32(const void* p) {
    uint32_t a;
    asm("{ .reg .u64 t; cvta.to.shared.u64 t, %1; cvt.u32.u64 %0, t; }" : "=r"(a) : "l"(p));
    return a;
}
__device__ __forceinline__ void cp16(uint32_t dst, const void* src) {
    asm volatile("cp.async.cg.shared.global [%0], [%1], 16;" :: "r"(dst), "l"(src));
}
template<int N> __device__ __forceinline__ void cpwait() {
    asm volatile("cp.async.wait_group %0;" :: "n"(N) : "memory");
}
__device__ __forceinline__ void ldsm4(uint32_t* r, uint32_t addr) {
    asm volatile("ldmatrix.sync.aligned.m8n8.x4.shared.b16 {%0,%1,%2,%3}, [%4];"
                 : "=r"(r[0]), "=r"(r[1]), "=r"(r[2]), "=r"(r[3]) : "r"(addr));
}
__device__ __forceinline__ void ldsm4t(uint32_t* r, uint32_t addr) {
    asm volatile("ldmatrix.sync.aligned.m8n8.x4.trans.shared.b16 {%0,%1,%2,%3}, [%4];"
                 : "=r"(r[0]), "=r"(r[1]), "=r"(r[2]), "=r"(r[3]) : "r"(addr));
}
__device__ __forceinline__ void mma16816h(float* c, const uint32_t* a, const uint32_t* b) {
    asm volatile(
        "mma.sync.aligned.m16n8k16.row.col.f32.f16.f16.f32 "
        "{%0,%1,%2,%3}, {%4,%5,%6,%7}, {%8,%9}, {%0,%1,%2,%3};"
        : "+f"(c[0]), "+f"(c[1]), "+f"(c[2]), "+f"(c[3])
        : "r"(a[0]), "r"(a[1]), "r"(a[2]), "r"(a[3]), "r"(b[0]), "r"(b[1]));
}
__device__ __forceinline__ float ex2f(float x) {
    float y; asm("ex2.approx.ftz.f32 %0, %1;" : "=f"(y) : "f"(x)); return y;
}
__device__ __forceinline__ uint32_t pack_hf2(float a, float b) {
    __half2 h; h.x = __float2half(a); h.y = __float2half(b);
    return *reinterpret_cast<uint32_t*>(&h);
}

// ---------------- mega prep kernel -------------------------------------------
// blocks [0,4096): convert x -> fp16. [4096,16384): weight fp16 transposes.
// [16384]: bias concat.
__global__ __launch_bounds__(256)
void prep_all(const float* __restrict__ x,
              const float* __restrict__ Wq, const float* __restrict__ Wk,
              const float* __restrict__ Wv, const float* __restrict__ Wo,
              const float* __restrict__ W1, const float* __restrict__ W2,
              const float* __restrict__ bq, const float* __restrict__ bk,
              const float* __restrict__ bv)
{
    __shared__ float t[32][33];
    const int blk = blockIdx.x;
    const int tid = threadIdx.x;

    if (blk < 4096) {                       // ---- convert x (2 float4 / thread)
        int i = blk * 512 + tid * 2;
        float4 v0 = reinterpret_cast<const float4*>(x)[i];
        float4 v1 = reinterpret_cast<const float4*>(x)[i + 1];
        __half2 a, b, c, d;
        a.x = __float2half(v0.x); a.y = __float2half(v0.y);
        b.x = __float2half(v0.z); b.y = __float2half(v0.w);
        c.x = __float2half(v1.x); c.y = __float2half(v1.y);
        d.x = __float2half(v1.z); d.y = __float2half(v1.w);
        reinterpret_cast<__half2*>(g_x)[2*i]     = a;
        reinterpret_cast<__half2*>(g_x)[2*i + 1] = b;
        reinterpret_cast<__half2*>(g_x)[2*i + 2] = c;
        reinterpret_cast<__half2*>(g_x)[2*i + 3] = d;
        return;
    }
    if (blk == 16384) {                     // ---- bias concat
        for (int i = tid; i < NQKV; i += 256)
            g_bqkv[i] = (i < 1024) ? bq[i] : (i < 2048) ? bk[i-1024] : bv[i-2048];
        return;
    }

    int b = blk - 4096;
    const float* W; __half* hT; int Kd, Nd;
    if      (b < 1024)  { W = Wq; hT = g_wqkv;              Kd = CD; Nd = CD; }
    else if (b < 2048)  { W = Wk; hT = g_wqkv + 1024u*CD;   Kd = CD; Nd = CD; b -= 1024; }
    else if (b < 3072)  { W = Wv; hT = g_wqkv + 2048u*CD;   Kd = CD; Nd = CD; b -= 2048; }
    else if (b < 4096)  { W = Wo; hT = g_wo; Kd = CD; Nd = CD; b -= 3072; }
    else if (b < 8192)  { W = W1; hT = g_w1; Kd = CD; Nd = CF; b -= 4096; }
    else                { W = W2; hT = g_w2; Kd = CF; Nd = CD; b -= 8192; }

    const int nb = Nd / 32;
    const int n0 = (b % nb) * 32, k0 = (b / nb) * 32;
    const int tx = tid & 31, ty = tid >> 5;
    for (int i = ty; i < 32; i += 8)
        t[i][tx] = W[(size_t)(k0 + i) * Nd + n0 + tx];
    __syncthreads();
    for (int i = ty; i < 32; i += 8)
        hT[(size_t)(n0 + i) * Kd + k0 + tx] = __float2half(t[tx][i]);
}

// ---------------- plain fp16 HGEMM -------------------------------------------
// C[M,N] = A[M,K] @ B[N,K]^T + bias.  128 thr, 4 warps, 64x64 warp tiles,
// 4-stage ring (64KB).  EPI: 0 = fp32 C, 1 = fp16, 2 = relu + fp16
template<int EPI>
__global__ __launch_bounds__(128, 2)
void hgemm_fp16(const __half* __restrict__ A, const __half* __restrict__ B,
                const float* __restrict__ bias, float* __restrict__ C,
                __half* __restrict__ Ch, int M, int N, int K)
{
    extern __shared__ __align__(1024) char smraw[];
    const uint32_t sbase = smem_u32(smraw);

    const int tid  = threadIdx.x;
    const int lane = tid & 31;
    const int wid  = tid >> 5;
    const int warp_m = wid & 1;
    const int warp_n = wid >> 1;
    const int brow = blockIdx.y, bcol = blockIdx.x;

    const int lr = tid >> 2;
    const int lc = tid & 3;
    const int KC = K >> 5;

    uint32_t swr[4];
    size_t agr[4], bgr[4];
    #pragma unroll
    for (int rr = 0; rr < 4; ++rr) {
        int r = lr + rr * 32;
        int key = (r >> 1) & 3;
        swr[rr] = (uint32_t)r * 64u + (uint32_t)((lc ^ key) << 4);
        agr[rr] = (size_t)(brow * 128 + r) * (size_t)K;
        bgr[rr] = (size_t)(bcol * 128 + r) * (size_t)K;
    }

    uint32_t a_rb[4]; int a_key[4];
    #pragma unroll
    for (int mt = 0; mt < 4; ++mt) {
        int r = warp_m * 64 + mt * 16 + (lane & 15);
        a_rb[mt] = (uint32_t)r * 64u;
        a_key[mt] = (r >> 1) & 3;
    }
    const int a_ch = lane >> 4;
    uint32_t b_rb[4]; int b_key[4];
    #pragma unroll
    for (int np = 0; np < 4; ++np) {
        int r = warp_n * 64 + np * 16 + (lane & 7) + ((lane >> 4) & 1) * 8;
        b_rb[np] = (uint32_t)r * 64u;
        b_key[np] = (r >> 1) & 3;
    }
    const int b_ch = (lane >> 3) & 1;

    float acc[4][8][4];
    #pragma unroll
    for (int mt = 0; mt < 4; ++mt)
        #pragma unroll
        for (int nt = 0; nt < 8; ++nt)
            #pragma unroll
            for (int r = 0; r < 4; ++r) acc[mt][nt][r] = 0.f;

    // stage = A(8KB) | B(8KB)
    auto load_stage = [&](int kk, int s) {
        const size_t ko = (size_t)kk * 32 + (size_t)lc * 8;
        const uint32_t st = sbase + (uint32_t)s * 16384u;
        #pragma unroll
        for (int rr = 0; rr < 4; ++rr) {
            cp16(st +         swr[rr], A + agr[rr] + ko);
            cp16(st + 8192u + swr[rr], B + bgr[rr] + ko);
        }
        asm volatile("cp.async.commit_group;" ::: "memory");
    };

    load_stage(0, 0);
    if (KC > 1) load_stage(1, 1);
    if (KC > 2) load_stage(2, 2);

    for (int t = 0; t < KC; ++t) {
        if (t + 2 < KC) cpwait<2>(); else if (t + 1 < KC) cpwait<1>(); else cpwait<0>();
        __syncthreads();
        if (t + 3 < KC) load_stage(t + 3, (t + 3) & 3);

        const uint32_t st = sbase + (uint32_t)(t & 3) * 16384u;
        #pragma unroll
        for (int ks = 0; ks < 2; ++ks) {
            uint32_t bf[4][4];
            #pragma unroll
            for (int np = 0; np < 4; ++np)
                ldsm4(bf[np], st + 8192u + b_rb[np] +
                      (uint32_t)((((ks << 1) + b_ch) ^ b_key[np]) << 4));
            uint32_t af[4][4];
            #pragma unroll
            for (int mt = 0; mt < 4; ++mt)
                ldsm4(af[mt], st + a_rb[mt] +
                      (uint32_t)((((ks << 1) + a_ch) ^ a_key[mt]) << 4));
            #pragma unroll
            for (int mt = 0; mt < 4; ++mt)
                #pragma unroll
                for (int nt = 0; nt < 8; ++nt)
                    mma16816h(acc[mt][nt], af[mt], &bf[nt >> 1][(nt & 1) * 2]);
        }
    }

    const int ng_base = bcol * 128 + warp_n * 64 + (lane & 3) * 2;
    const int mg_base = brow * 128 + warp_m * 64 + (lane >> 2);
    #pragma unroll
    for (int nt = 0; nt < 8; ++nt) {
        const int n = ng_base + nt * 8;
        const float2 bb = *reinterpret_cast<const float2*>(&bias[n]);
        #pragma unroll
        for (int mt = 0; mt < 4; ++mt) {
            const int m0 = mg_base + mt * 16;
            float v0 = acc[mt][nt][0] + bb.x, v1 = acc[mt][nt][1] + bb.y;
            float v2 = acc[mt][nt][2] + bb.x, v3 = acc[mt][nt][3] + bb.y;
            if (EPI == 2) {
                v0 = fmaxf(v0, 0.f); v1 = fmaxf(v1, 0.f);
                v2 = fmaxf(v2, 0.f); v3 = fmaxf(v3, 0.f);
            }
            if (EPI == 0) {
                float2 o0{v0, v1}, o1{v2, v3};
                *reinterpret_cast<float2*>(&C[(size_t)m0 * N + n])       = o0;
                *reinterpret_cast<float2*>(&C[(size_t)(m0 + 8) * N + n]) = o1;
            } else {
                *reinterpret_cast<uint32_t*>(&Ch[(size_t)m0 * N + n])       = pack_hf2(v0, v1);
                *reinterpret_cast<uint32_t*>(&Ch[(size_t)(m0 + 8) * N + n]) = pack_hf2(v2, v3);
            }
        }
    }
}

// ---------------- Flash attention, fp16 single-pass (causal) -----------------
__global__ __launch_bounds__(128)
void flash_hmma(const __half* __restrict__ QKV, __half* __restrict__ O)
{
    extern __shared__ __align__(1024) char smraw[];
    const uint32_t sb = smem_u32(smraw);
    const uint32_t QHs = sb;

    const int qt = (int)gridDim.x - 1 - (int)blockIdx.x;
    const int b  = blockIdx.y >> 4, h = blockIdx.y & 15;
    const int tid = threadIdx.x, lane = tid & 31, warp = tid >> 5;

    const size_t qbase = (size_t)b * CS * NQKV + (size_t)h * CDK;
    const size_t obase = (size_t)b * CS * CD   + (size_t)h * CDK;

    auto load_tile = [&](uint32_t dst, const __half* src, size_t base, int tile) {
        const __half* g = src + base + (size_t)tile * 64 * NQKV;
        #pragma unroll
        for (int i = 0; i < 4; ++i) {
            int id = tid + i * 128;
            int r = id >> 3, c = id & 7;
            cp16(dst + (uint32_t)r * 128u + (uint32_t)((c ^ (r & 7)) << 4),
                 g + (size_t)r * NQKV + c * 8);
        }
    };
    auto load_kv = [&](int kt) {
        uint32_t s = sb + 8192u + (uint32_t)(kt & 1) * 16384u;
        load_tile(s,         QKV, qbase + 1024, kt);   // K
        load_tile(s + 8192u, QKV, qbase + 2048, kt);   // V
        asm volatile("cp.async.commit_group;" ::: "memory");
    };

    load_tile(QHs, QKV, qbase, qt);
    load_kv(0);
    cpwait<0>(); __syncthreads();

    uint32_t qf[4][4];
    {
        int r = warp * 16 + (lane & 15);
        uint32_t ro = (uint32_t)r * 128u;
        int key = r & 7;
        #pragma unroll
        for (int ks = 0; ks < 4; ++ks)
            ldsm4(qf[ks], QHs + ro + (uint32_t)(((ks * 2 + (lane >> 4)) ^ key) << 4));
    }

    float m0 = -1e30f, m1 = -1e30f, l0 = 0.f, l1 = 0.f;
    float oacc[8][4];
    #pragma unroll
    for (int nt = 0; nt < 8; ++nt)
        #pragma unroll
        for (int r = 0; r < 4; ++r) oacc[nt][r] = 0.f;

    const float c1 = 0.18033688011112042f;
    const int r0t = warp * 16 + (lane >> 2);

    for (int kt = 0; kt <= qt; ++kt) {
        if (kt + 1 <= qt) load_kv(kt + 1);
        if (kt > 0) {
            if (kt + 1 <= qt) cpwait<1>(); else cpwait<0>();
            __syncthreads();
        }
        const uint32_t KB = sb + 8192u + (uint32_t)(kt & 1) * 16384u;
        const uint32_t VB = KB + 8192u;

        float sacc[8][4];
        #pragma unroll
        for (int nt = 0; nt < 8; ++nt)
            #pragma unroll
            for (int r = 0; r < 4; ++r) sacc[nt][r] = 0.f;

        #pragma unroll
        for (int ks = 0; ks < 4; ++ks) {
            uint32_t bf[4][4];
            #pragma unroll
            for (int np = 0; np < 4; ++np) {
                int rr = np * 16 + (lane & 7) + ((lane >> 4) & 1) * 8;
                uint32_t chunk = (uint32_t)(ks * 2 + ((lane >> 3) & 1));
                ldsm4(bf[np], KB + (uint32_t)rr * 128u + ((chunk ^ (uint32_t)(rr & 7)) << 4));
            }
            #pragma unroll
            for (int nt = 0; nt < 8; ++nt)
                mma16816h(sacc[nt], qf[ks], &bf[nt >> 1][(nt & 1) * 2]);
        }

        const bool diag = (kt == qt);
        float rm0 = -1e30f, rm1 = -1e30f;
        #pragma unroll
        for (int nt = 0; nt < 8; ++nt) {
            const int cb = nt * 8 + 2 * (lane & 3);
            #pragma unroll
            for (int j = 0; j < 2; ++j) {
                float v = sacc[nt][j] * c1;
                if (diag && cb + j > r0t) v = -1e30f;
                sacc[nt][j] = v; rm0 = fmaxf(rm0, v);
                float w = sacc[nt][2 + j] * c1;
                if (diag && cb + j > r0t + 8) w = -1e30f;
                sacc[nt][2 + j] = w; rm1 = fmaxf(rm1, w);
            }
        }
        rm0 = fmaxf(rm0, __shfl_xor_sync(0xffffffffu, rm0, 1));
        rm0 = fmaxf(rm0, __shfl_xor_sync(0xffffffffu, rm0, 2));
        rm1 = fmaxf(rm1, __shfl_xor_sync(0xffffffffu, rm1, 1));
        rm1 = fmaxf(rm1, __shfl_xor_sync(0xffffffffu, rm1, 2));
        const float mn0 = fmaxf(m0, rm0), mn1 = fmaxf(m1, rm1);
        const float corr0 = ex2f(m0 - mn0), corr1 = ex2f(m1 - mn1);
        m0 = mn0; m1 = mn1;

        // P in fp16; l accumulated from the ROUNDED values (bias-free P/l)
        float ps0 = 0.f, ps1 = 0.f;
        uint32_t pf[4][4];
        #pragma unroll
        for (int nt = 0; nt < 8; ++nt) {
            float p0 = ex2f(sacc[nt][0] - m0);
            float p1 = ex2f(sacc[nt][1] - m0);
            float p2 = ex2f(sacc[nt][2] - m1);
            float p3 = ex2f(sacc[nt][3] - m1);
            float h0 = __half2float(__float2half(p0));
            float h1 = __half2float(__float2half(p1));
            float h2 = __half2float(__float2half(p2));
            float h3 = __half2float(__float2half(p3));
            ps0 += h0 + h1; ps1 += h2 + h3;
            const int kc = nt >> 1, base = (nt & 1) * 2;
            pf[kc][base]     = pack_hf2(h0, h1);
            pf[kc][base + 1] = pack_hf2(h2, h3);
        }
        ps0 += __shfl_xor_sync(0xffffffffu, ps0, 1);
        ps0 += __shfl_xor_sync(0xffffffffu, ps0, 2);
        ps1 += __shfl_xor_sync(0xffffffffu, ps1, 1);
        ps1 += __shfl_xor_sync(0xffffffffu, ps1, 2);
        l0 = l0 * corr0 + ps0;
        l1 = l1 * corr1 + ps1;

        #pragma unroll
        for (int nt = 0; nt < 8; ++nt) {
            oacc[nt][0] *= corr0; oacc[nt][1] *= corr0;
            oacc[nt][2] *= corr1; oacc[nt][3] *= corr1;
        }

        const int vj  = lane >> 3, vlp = lane & 7;
        #pragma unroll
        for (int kc = 0; kc < 4; ++kc) {
            const int vrow = kc * 16 + (vj & 1) * 8 + vlp;
            const uint32_t vro = (uint32_t)vrow * 128u;
            const uint32_t vkey = (uint32_t)(vrow & 7);
            uint32_t vf[4][4];
            #pragma unroll
            for (int vb = 0; vb < 4; ++vb) {
                uint32_t chunk = (uint32_t)(vb * 2 + (vj >> 1));
                ldsm4t(vf[vb], VB + vro + ((chunk ^ vkey) << 4));
            }
            #pragma unroll
            for (int nt = 0; nt < 8; ++nt)
                mma16816h(oacc[nt], pf[kc], &vf[nt >> 1][(nt & 1) * 2]);
        }
        __syncthreads();
    }

    const float inv0 = 1.f / l0, inv1 = 1.f / l1;
    const size_t row0 = obase + (size_t)(qt * 64 + r0t) * CD;
    const size_t row1 = row0 + (size_t)8 * CD;
    #pragma unroll
    for (int nt = 0; nt < 8; ++nt) {
        const int cb = nt * 8 + 2 * (lane & 3);
        *reinterpret_cast<uint32_t*>(&O[row0 + cb]) =
            pack_hf2(oacc[nt][0] * inv0, oacc[nt][1] * inv0);
        *reinterpret_cast<uint32_t*>(&O[row1 + cb]) =
            pack_hf2(oacc[nt][2] * inv1, oacc[nt][3] * inv1);
    }
}

// ---------------- residual + LayerNorm (optional fp16 output) ----------------
__global__ __launch_bounds__(256)
void residual_ln(const float* __restrict__ x, const float* __restrict__ r,
                 const float* __restrict__ gamma, const float* __restrict__ beta,
                 float* __restrict__ out, __half* __restrict__ outh)
{
    const int row = blockIdx.x;
    const int tid = threadIdx.x;
    const float4 a = reinterpret_cast<const float4*>(x + (size_t)row * CD)[tid];
    const float4 c = reinterpret_cast<const float4*>(r + (size_t)row * CD)[tid];
    float v0 = a.x + c.x, v1 = a.y + c.y, v2 = a.z + c.z, v3 = a.w + c.w;
    float s  = v0 + v1 + v2 + v3;
    float sq = v0 * v0 + v1 * v1 + v2 * v2 + v3 * v3;

    #pragma unroll
    for (int o = 16; o; o >>= 1) {
        s  += __shfl_xor_sync(0xffffffffu, s,  o);
        sq += __shfl_xor_sync(0xffffffffu, sq, o);
    }
    __shared__ float ss[8], sg[8];
    const int w = tid >> 5, lane = tid & 31;
    if (lane == 0) { ss[w] = s; sg[w] = sq; }
    __syncthreads();
    if (w == 0) {
        s  = (lane < 8) ? ss[lane] : 0.f;
        sq = (lane < 8) ? sg[lane] : 0.f;
        #pragma unroll
        for (int o = 4; o; o >>= 1) {
            s  += __shfl_xor_sync(0xffffffffu, s,  o);
            sq += __shfl_xor_sync(0xffffffffu, sq, o);
        }
        if (lane == 0) { ss[0] = s; sg[0] = sq; }
    }
    __syncthreads();
    s = ss[0]; sq = sg[0];

    const float mu  = s * (1.f / CD);
    const float var = sq * (1.f / CD) - mu * mu;
    const float inv = rsqrtf(var + 1e-5f);

    const float4 gv = reinterpret_cast<const float4*>(gamma)[tid];
    const float4 bv = reinterpret_cast<const float4*>(beta)[tid];
    float4 o4;
    o4.x = (v0 - mu) * inv * gv.x + bv.x;
    o4.y = (v1 - mu) * inv * gv.y + bv.y;
    o4.z = (v2 - mu) * inv * gv.z + bv.z;
    o4.w = (v3 - mu) * inv * gv.w + bv.w;
    reinterpret_cast<float4*>(out + (size_t)row * CD)[tid] = o4;

    if (outh) {
        __half2 h0, h1;
        h0.x = __float2half(o4.x); h0.y = __float2half(o4.y);
        h1.x = __float2half(o4.z); h1.y = __float2half(o4.w);
        reinterpret_cast<__half2*>(outh + (size_t)row * CD)[2*tid]   = h0;
        reinterpret_cast<__half2*>(outh + (size_t)row * CD)[2*tid+1] = h1;
    }
}

// ---------------- launch -----------------------------------------------------
extern "C" void kernel_launch(void* const* d_in, const int* in_sizes, int n_in,
                              void* d_out, int out_size)
{
    const float* x  = (const float*)d_in[0];
    const float* Wq = (const float*)d_in[2];
    const float* bq = (const float*)d_in[3];
    const float* Wk = (const float*)d_in[4];
    const float* bk = (const float*)d_in[5];
    const float* Wv = (const float*)d_in[6];
    const float* bv = (const float*)d_in[7];
    const float* Wo = (const float*)d_in[8];
    const float* bo = (const float*)d_in[9];
    const float* g1 = (const float*)d_in[10];
    const float* b1 = (const float*)d_in[11];
    const float* W1 = (const float*)d_in[12];
    const float* c1 = (const float*)d_in[13];
    const float* W2 = (const float*)d_in[14];
    const float* c2 = (const float*)d_in[15];
    const float* g2 = (const float*)d_in[16];
    const float* b2 = (const float*)d_in[17];
    float* out = (float*)d_out;

    float *pr, *x1, *ff, *bqkv;
    cudaGetSymbolAddress((void**)&pr, g_pr);
    cudaGetSymbolAddress((void**)&x1, g_x1);
    cudaGetSymbolAddress((void**)&ff, g_ff);
    cudaGetSymbolAddress((void**)&bqkv, g_bqkv);

    __half *xh,*qkv,*ao,*x1h,*hh,*wqkv,*wo,*w1,*w2;
    cudaGetSymbolAddress((void**)&xh,   g_x);
    cudaGetSymbolAddress((void**)&qkv,  g_qkv);
    cudaGetSymbolAddress((void**)&ao,   g_ao);
    cudaGetSymbolAddress((void**)&x1h,  g_x1h);
    cudaGetSymbolAddress((void**)&hh,   g_hh);
    cudaGetSymbolAddress((void**)&wqkv, g_wqkv);
    cudaGetSymbolAddress((void**)&wo,   g_wo);
    cudaGetSymbolAddress((void**)&w1,   g_w1);
    cudaGetSymbolAddress((void**)&w2,   g_w2);

    cudaFuncSetAttribute(flash_hmma, cudaFuncAttributeMaxDynamicSharedMemorySize, FA_SMEM);
    cudaFuncSetAttribute(hgemm_fp16<0>, cudaFuncAttributeMaxDynamicSharedMemorySize, HF_SMEM);
    cudaFuncSetAttribute(hgemm_fp16<1>, cudaFuncAttributeMaxDynamicSharedMemorySize, HF_SMEM);
    cudaFuncSetAttribute(hgemm_fp16<2>, cudaFuncAttributeMaxDynamicSharedMemorySize, HF_SMEM);

    prep_all<<<16385, 256>>>(x, Wq, Wk, Wv, Wo, W1, W2, bq, bk, bv);

    dim3 gQKV(NQKV / 128, MTOT / 128);
    dim3 gD(CD / 128, MTOT / 128);
    dim3 gF(CF / 128, MTOT / 128);

    hgemm_fp16<1><<<gQKV, 128, HF_SMEM>>>(xh, wqkv, bqkv, nullptr, qkv, MTOT, NQKV, CD);

    flash_hmma<<<dim3(CS / 64, CB * CH), 128, FA_SMEM>>>(qkv, ao);

    hgemm_fp16<0><<<gD, 128, HF_SMEM>>>(ao, wo, bo, pr, nullptr, MTOT, CD, CD);
    residual_ln<<<MTOT, 256>>>(x, pr, g1, b1, x1, x1h);

    hgemm_fp16<2><<<gF, 128, HF_SMEM>>>(x1h, w1, c1, nullptr, hh, MTOT, CF, CD);
    hgemm_fp16<0><<<gD, 128, HF_SMEM>>>(hh, w2, c2, ff, nullptr, MTOT, CD, CF);
    residual_ln<<<MTOT, 256>>>(x1, ff, g2, b2, out, nullptr);
}